// round 12
// baseline (speedup 1.0000x reference)
#include <cuda_runtime.h>
#include <cuda_bf16.h>
#include <cstdint>

// ---------------- problem constants ----------------
#define Bn   8
#define L1n  7
#define L2n  3
#define N1n  2048
#define N2n  512
#define CINn 512
#define MIDn 256
#define OUTn 512
#define CORn 128
#define Kt   3
#define KMID (Kt*MIDn)   // 768
#define NSL  (L2n*Kt)    // 9
#define KSP  (MIDn+CORn) // 384

__constant__ int c_start[7] = {0,1,2,4,5,7,8};
__constant__ int c_cnt[7]   = {1,1,2,1,2,1,1};

// ---------------- scratch (device globals) ----------------
__device__ float g_tf[(size_t)Bn*L2n*KMID*N2n];      // temporal GEMM out (b,t2,o,n)
__device__ float g_scale[NSL*MIDn];
__device__ float g_shift[NSL*MIDn];
__device__ int   g_idx[(size_t)Bn*L1n*N1n*3];
__device__ float g_w[(size_t)Bn*L1n*N1n*3];
__device__ __align__(16) float g_P[(size_t)NSL*Bn*N2n*OUTn];  // P = seedf @ Ws1^T (s,b,n2,outc)
// BN partial sums: slot = ((z*4+bx)*2+half)*KMID + row   (24*4*2*768)
__device__ float g_psum[24*4*2*KMID];
__device__ float g_psq[24*4*2*KMID];
// bf16 split operands (16B aligned for cp.async)
__device__ __align__(16) __nv_bfloat16 g_WtHi[KMID*CINn], g_WtLo[KMID*CINn];
__device__ __align__(16) __nv_bfloat16 g_WsHi[OUTn*KSP],  g_WsLo[OUTn*KSP];
__device__ __align__(16) __nv_bfloat16 g_ftHi[(size_t)Bn*L2n*N2n*CINn];
__device__ __align__(16) __nv_bfloat16 g_ftLo[(size_t)Bn*L2n*N2n*CINn];   // (z,n,c)
__device__ __align__(16) __nv_bfloat16 g_sfHi[(size_t)NSL*Bn*N2n*MIDn];
__device__ __align__(16) __nv_bfloat16 g_sfLo[(size_t)NSL*Bn*N2n*MIDn];   // seedf (s,b,n,c)
__device__ __align__(16) __nv_bfloat16 g_ofHi[(size_t)Bn*L1n*N1n*CORn];
__device__ __align__(16) __nv_bfloat16 g_ofLo[(size_t)Bn*L1n*N1n*CORn];   // (z,n,c)

// ===================== PTX helpers (base sm_103-safe) =====================
__device__ __forceinline__ uint32_t smem_u32(const void* p) {
    uint32_t a;
    asm("{ .reg .u64 t; cvta.to.shared.u64 t, %1; cvt.u32.u64 %0, t; }" : "=r"(a) : "l"(p));
    return a;
}
__device__ __forceinline__ void cp16(uint32_t dst, const void* src) {
    asm volatile("cp.async.cg.shared.global [%0], [%1], 16;" :: "r"(dst), "l"(src));
}
__device__ __forceinline__ void ldm4(uint32_t* r, uint32_t addr) {
    asm volatile("ldmatrix.sync.aligned.m8n8.x4.shared.b16 {%0,%1,%2,%3}, [%4];"
                 : "=r"(r[0]), "=r"(r[1]), "=r"(r[2]), "=r"(r[3]) : "r"(addr));
}
__device__ __forceinline__ void mma16816(float* d, const uint32_t* a, const uint32_t* b) {
    asm volatile("mma.sync.aligned.m16n8k16.row.col.f32.bf16.bf16.f32 "
                 "{%0,%1,%2,%3}, {%4,%5,%6,%7}, {%8,%9}, {%0,%1,%2,%3};"
                 : "+f"(d[0]), "+f"(d[1]), "+f"(d[2]), "+f"(d[3])
                 : "r"(a[0]), "r"(a[1]), "r"(a[2]), "r"(a[3]), "r"(b[0]), "r"(b[1]));
}

// =====================================================================
// Fused bf16x2 split GEMM core. Tile 128x128, BK=32, 256 threads.
// acc += Ahi*Bhi + Alo*Bhi + Ahi*Blo per staged K-chunk.
// =====================================================================
#define ROWB 80                    // 64B data + 16B pad
#define TILEB (128*ROWB)           // 10240
#define STAGEB (4*TILEB)           // 40960
#define GEMM_SMEM (2*STAGEB)       // 81920

struct GemmCtx {
    const char *pAh, *pAl, *pBh, *pBl;
    int ldA, ldB;
    int m0, n0;
    uint32_t sbase;
    int tid, lane, wid, wm, wn;
};

__device__ __forceinline__ void gemm_loadTile(const GemmCtx& g, int c, int buf) {
    const int k0 = c << 5;
    const uint32_t sd = g.sbase + buf * STAGEB;
#pragma unroll
    for (int t = 0; t < 8; t++) {
        const int tile = t >> 1;
        const int within = ((t & 1) << 8) + g.tid;
        const int row = within >> 2, colB = (within & 3) << 4;
        const char* bp = (tile == 0) ? g.pAh : (tile == 1) ? g.pAl
                       : (tile == 2) ? g.pBh : g.pBl;
        const int rowg = ((tile < 2) ? g.m0 : g.n0) + row;
        const int ld = (tile < 2) ? g.ldA : g.ldB;
        cp16(sd + tile * TILEB + row * ROWB + colB,
             bp + ((long)rowg * ld + k0) * 2 + colB);
    }
    asm volatile("cp.async.commit_group;" ::: "memory");
}

__device__ __forceinline__ void gemm_computeTile(const GemmCtx& g, int buf,
                                                 float acc[2][8][4]) {
    const uint32_t sAh = g.sbase + buf * STAGEB;
    const uint32_t sAl = sAh + TILEB;
    const uint32_t sBh = sAl + TILEB;
    const uint32_t sBl = sBh + TILEB;
    const int lane = g.lane;
#pragma unroll
    for (int ks = 0; ks < 2; ks++) {
        uint32_t aH[2][4], aL[2][4], bT[4][4];
        const uint32_t aoff0 = (g.wm + (lane & 15)) * ROWB + ks * 32 + (lane >> 4) * 16;
        ldm4(aH[0], sAh + aoff0);
        ldm4(aH[1], sAh + aoff0 + 16 * ROWB);
        ldm4(aL[0], sAl + aoff0);
        ldm4(aL[1], sAl + aoff0 + 16 * ROWB);
#pragma unroll
        for (int ib = 0; ib < 4; ib++) {
            const uint32_t row = g.wn + ib * 16 + (lane & 7) + ((lane & 16) ? 8 : 0);
            ldm4(bT[ib], sBh + row * ROWB + ks * 32 + ((lane & 8) ? 16 : 0));
        }
#pragma unroll
        for (int im = 0; im < 2; im++)
#pragma unroll
            for (int in = 0; in < 8; in++)
                mma16816(acc[im][in], aH[im], bT[in >> 1] + (in & 1) * 2);
#pragma unroll
        for (int im = 0; im < 2; im++)
#pragma unroll
            for (int in = 0; in < 8; in++)
                mma16816(acc[im][in], aL[im], bT[in >> 1] + (in & 1) * 2);
#pragma unroll
        for (int ib = 0; ib < 4; ib++) {
            const uint32_t row = g.wn + ib * 16 + (lane & 7) + ((lane & 16) ? 8 : 0);
            ldm4(bT[ib], sBl + row * ROWB + ks * 32 + ((lane & 8) ? 16 : 0));
        }
#pragma unroll
        for (int im = 0; im < 2; im++)
#pragma unroll
            for (int in = 0; in < 8; in++)
                mma16816(acc[im][in], aH[im], bT[in >> 1] + (in & 1) * 2);
    }
}

__device__ __forceinline__ void gemm_init(GemmCtx& g,
    const __nv_bfloat16* Ahi, const __nv_bfloat16* Alo,
    const __nv_bfloat16* Bhi, const __nv_bfloat16* Blo,
    int ldA, int ldB, long strideA, long strideB, void* smem)
{
    const int z = blockIdx.z;
    g.tid = threadIdx.x; g.lane = g.tid & 31; g.wid = g.tid >> 5;
    g.m0 = blockIdx.y * 128; g.n0 = blockIdx.x * 128;
    g.wm = (g.wid & 3) * 32; g.wn = (g.wid >> 2) * 64;
    g.sbase = smem_u32(smem);
    g.pAh = (const char*)(Ahi + (long)z * strideA);
    g.pAl = (const char*)(Alo + (long)z * strideA);
    g.pBh = (const char*)(Bhi + (long)z * strideB);
    g.pBl = (const char*)(Blo + (long)z * strideB);
    g.ldA = ldA; g.ldB = ldB;
}

// single-sync mainloop: load(c+1) issued AFTER the barrier (all warps done
// reading the buffer it overwrites), overlapping with compute(c).
__device__ __forceinline__ void gemm_mainloop(const GemmCtx& g, int Ktot,
                                              float acc[2][8][4]) {
    const int kch = Ktot >> 5;
    gemm_loadTile(g, 0, 0);
    for (int c = 0; c < kch; c++) {
        asm volatile("cp.async.wait_group 0;" ::: "memory");
        __syncthreads();
        if (c + 1 < kch) gemm_loadTile(g, c + 1, (c + 1) & 1);
        gemm_computeTile(g, c & 1, acc);
    }
}

// ---------------- generic GEMM (temporal + P); optional BN partials ----------
__global__ __launch_bounds__(256, 2)
void gemm_mma_kernel(const __nv_bfloat16* __restrict__ Ahi,
                     const __nv_bfloat16* __restrict__ Alo,
                     const __nv_bfloat16* __restrict__ Bhi,
                     const __nv_bfloat16* __restrict__ Blo,
                     float* __restrict__ C,
                     int N, int Ktot, int ldA, int ldB,
                     long strideA, long strideB, long strideC,
                     float* __restrict__ psum, float* __restrict__ psq)
{
    extern __shared__ __align__(16) char smem[];
    GemmCtx g;
    gemm_init(g, Ahi, Alo, Bhi, Blo, ldA, ldB, strideA, strideB, smem);

    float acc[2][8][4];
#pragma unroll
    for (int i = 0; i < 2; i++)
#pragma unroll
        for (int j = 0; j < 8; j++)
#pragma unroll
            for (int q = 0; q < 4; q++) acc[i][j][q] = 0.f;

    gemm_mainloop(g, Ktot, acc);

    float* cz = C + (long)blockIdx.z * strideC;
#pragma unroll
    for (int im = 0; im < 2; im++) {
        const int row = g.m0 + g.wm + im * 16 + (g.lane >> 2);
#pragma unroll
        for (int in = 0; in < 8; in++) {
            const int col = g.n0 + g.wn + in * 8 + (g.lane & 3) * 2;
            *(float2*)(cz + (long)row * N + col) =
                make_float2(acc[im][in][0], acc[im][in][1]);
            *(float2*)(cz + (long)(row + 8) * N + col) =
                make_float2(acc[im][in][2], acc[im][in][3]);
        }
    }

    // ---- optional BN partial sums (temporal GEMM only) ----
    if (psum) {
        const int half = g.wid >> 2;   // which 64-col half (wn/64)
        const long slot = (((long)blockIdx.z * 4 + blockIdx.x) * 2 + half) * KMID;
#pragma unroll
        for (int im = 0; im < 2; im++) {
#pragma unroll
            for (int rr = 0; rr < 2; rr++) {        // row r (+0) and r+8
                float s = 0.f, q = 0.f;
#pragma unroll
                for (int in = 0; in < 8; in++) {
                    const float v0 = acc[im][in][rr * 2];
                    const float v1 = acc[im][in][rr * 2 + 1];
                    s += v0 + v1;
                    q += v0 * v0 + v1 * v1;
                }
                s += __shfl_xor_sync(0xffffffffu, s, 1);
                q += __shfl_xor_sync(0xffffffffu, q, 1);
                s += __shfl_xor_sync(0xffffffffu, s, 2);
                q += __shfl_xor_sync(0xffffffffu, q, 2);
                if ((g.lane & 3) == 0) {
                    const int grow = g.m0 + g.wm + im * 16 + (g.lane >> 2) + rr * 8;
                    psum[slot + grow] = s;
                    psq[slot + grow]  = q;
                }
            }
        }
    }
}

// BN finalize: 2304 channels (t2, o) -> scale/shift
__global__ void bn_finalize_kernel(const float* __restrict__ gamma,
                                   const float* __restrict__ beta)
{
    const int t = blockIdx.x * 256 + threadIdx.x;
    if (t >= L2n * KMID) return;
    const int t2 = t / KMID, o = t % KMID;
    float S = 0.f, Q = 0.f;
    for (int b = 0; b < Bn; b++)
        for (int bx = 0; bx < 4; bx++)
            for (int h = 0; h < 2; h++) {
                const long slot = (((long)(b * 3 + t2) * 4 + bx) * 2 + h) * KMID + o;
                S += g_psum[slot];
                Q += g_psq[slot];
            }
    const float inv = 1.f / (float)(Bn * N2n);
    const float mean = S * inv;
    const float var = Q * inv - mean * mean;
    const float istd = rsqrtf(var + 1e-5f);
    const int k = o >> 8, c = o & 255;
    const int s = t2 * 3 + k;
    const float scl = gamma[c] * istd;
    g_scale[s * MIDn + c] = scl;
    g_shift[s * MIDn + c] = beta[c] - mean * scl;
}

// ---------------- C2 GEMM with fused interp-gather epilogue ----------------
// C[z][outc][n1] = (Ws2 @ ofeat)[outc][n1] + sum_k w_k * P[idx_k(n1)][outc]
// idx/w for the block's 128 anchors are prefetched into smem (coalesced),
// removing the dependent global idx load from every gather chain.
#define SMFP 132   // smem gather-tile pitch in floats (16B multiple)

__global__ __launch_bounds__(256, 2)
void gemm_c2_fused_kernel(const __nv_bfloat16* __restrict__ Ahi,
                          const __nv_bfloat16* __restrict__ Alo,
                          const __nv_bfloat16* __restrict__ Bhi,
                          const __nv_bfloat16* __restrict__ Blo,
                          float* __restrict__ C,
                          int N, int Ktot, int ldA, int ldB,
                          long strideA, long strideB, long strideC)
{
    extern __shared__ __align__(16) char smem[];
    __shared__ int   sidx[128 * 3];
    __shared__ float swt[128 * 3];
    GemmCtx g;
    gemm_init(g, Ahi, Alo, Bhi, Blo, ldA, ldB, strideA, strideB, smem);

    float acc[2][8][4];
#pragma unroll
    for (int i = 0; i < 2; i++)
#pragma unroll
        for (int j = 0; j < 8; j++)
#pragma unroll
            for (int q = 0; q < 4; q++) acc[i][j][q] = 0.f;

    gemm_mainloop(g, Ktot, acc);

    // prefetch idx/w for this block's 128 anchors (coalesced, 384 each)
    const int zz = blockIdx.z;
    {
        const long gbase = ((long)zz * N1n + g.n0) * 3;
#pragma unroll
        for (int i = 0; i < 2; i++) {
            const int t = g.tid + i * 256;
            if (t < 384) { sidx[t] = g_idx[gbase + t]; swt[t] = g_w[gbase + t]; }
        }
    }
    __syncthreads();   // GEMM smem reads done + prefetch visible

    // ---- gather stage: reuse smem as sm[anchor 0..127][outc 0..127] ----
    const int b = zz / L1n, t1 = zz % L1n;
    float (*smf)[SMFP] = (float(*)[SMFP])smem;
    const int lane = g.lane, wid = g.wid;

#pragma unroll
    for (int aa = 0; aa < 16; aa++) {
        const int a = wid * 16 + aa;
        float4 s = make_float4(0.f, 0.f, 0.f, 0.f);
#pragma unroll
        for (int k = 0; k < 3; k++) {
            const int j = sidx[a * 3 + k];          // smem broadcast
            const float wk = swt[a * 3 + k];
            const int sl = c_start[t1] + (j >> 9);
            const int n = j & 511;
            const float4 v = *(const float4*)(g_P +
                (((long)sl * Bn + b) * N2n + n) * OUTn + g.m0 + lane * 4);
            s.x = fmaf(wk, v.x, s.x);
            s.y = fmaf(wk, v.y, s.y);
            s.z = fmaf(wk, v.z, s.z);
            s.w = fmaf(wk, v.w, s.w);
        }
        *(float4*)(&smf[a][lane * 4]) = s;
    }
    __syncthreads();

    // ---- epilogue: out = acc + gathered interp ----
    float* cz = C + (long)zz * strideC;
#pragma unroll
    for (int im = 0; im < 2; im++) {
        const int rl = g.wm + im * 16 + (lane >> 2);     // outc local
        const int row = g.m0 + rl;
#pragma unroll
        for (int in = 0; in < 8; in++) {
            const int cl = g.wn + in * 8 + (lane & 3) * 2;  // anchor local
            const int col = g.n0 + cl;
            *(float2*)(cz + (long)row * N + col) = make_float2(
                acc[im][in][0] + smf[cl][rl],
                acc[im][in][1] + smf[cl + 1][rl]);
            *(float2*)(cz + (long)(row + 8) * N + col) = make_float2(
                acc[im][in][2] + smf[cl][rl + 8],
                acc[im][in][3] + smf[cl + 1][rl + 8]);
        }
    }
}

// =====================================================================
// bf16 hi/lo split helpers + prep kernels
// =====================================================================
__device__ __forceinline__ void bf16_split(float v, __nv_bfloat16& h, __nv_bfloat16& l) {
    h = __float2bfloat16(v);
    l = __float2bfloat16(v - __bfloat162float(h));
}

__global__ void split_kernel(const float* __restrict__ src,
                             __nv_bfloat16* __restrict__ hi,
                             __nv_bfloat16* __restrict__ lo, long n)
{
    const long i = (long)blockIdx.x * 256 + threadIdx.x;
    if (i < n) { __nv_bfloat16 h, l; bf16_split(src[i], h, l); hi[i] = h; lo[i] = l; }
}

// features (z,c=512,n=512) -> g_ft (z,n,c) hi/lo
__global__ void featT_kernel(const float* __restrict__ feat)
{
    __shared__ float sm[32][33];
    const int z = blockIdx.z, n0 = blockIdx.x * 32, c0 = blockIdx.y * 32;
    const int tx = threadIdx.x & 31, ty = threadIdx.x >> 5;
    const float* src = feat + (long)z * CINn * N2n;
#pragma unroll
    for (int i = 0; i < 4; i++)
        sm[ty + i * 8][tx] = src[(long)(c0 + ty + i * 8) * N2n + n0 + tx];
    __syncthreads();
#pragma unroll
    for (int i = 0; i < 4; i++) {
        const int n = n0 + ty + i * 8;
        __nv_bfloat16 h, l; bf16_split(sm[tx][ty + i * 8], h, l);
        const long a = ((long)z * N2n + n) * CINn + c0 + tx;
        g_ftHi[a] = h; g_ftLo[a] = l;
    }
}

// original_features (z,c=128,n=2048) -> g_of (z,n,c) hi/lo
__global__ void ofeatT_kernel(const float* __restrict__ ofeat)
{
    __shared__ float sm[32][33];
    const int z = blockIdx.z, n0 = blockIdx.x * 32, c0 = blockIdx.y * 32;
    const int tx = threadIdx.x & 31, ty = threadIdx.x >> 5;
    const float* src = ofeat + (long)z * CORn * N1n;
#pragma unroll
    for (int i = 0; i < 4; i++)
        sm[ty + i * 8][tx] = src[(long)(c0 + ty + i * 8) * N1n + n0 + tx];
    __syncthreads();
#pragma unroll
    for (int i = 0; i < 4; i++) {
        const int n = n0 + ty + i * 8;
        __nv_bfloat16 h, l; bf16_split(sm[tx][ty + i * 8], h, l);
        const long a = ((long)z * N1n + n) * CORn + c0 + tx;
        g_ofHi[a] = h; g_ofLo[a] = l;
    }
}

// BN apply + ReLU + transpose + split: g_tf (b,t2,o,n) -> g_sf (s,b,n,c) hi/lo
__global__ void bn_transpose_kernel()
{
    __shared__ float sm[32][33];
    const int s = blockIdx.z >> 3, b = blockIdx.z & 7;
    const int t2 = s / 3, k = s % 3;
    const int n0 = blockIdx.x * 32, c0 = blockIdx.y * 32;
    const int tx = threadIdx.x & 31, ty = threadIdx.x >> 5;

    const float* src = g_tf + ((long)(b * L2n + t2) * KMID + k * MIDn) * N2n;
#pragma unroll
    for (int i = 0; i < 4; i++) {
        const int cl = ty + i * 8;
        const int c = c0 + cl;
        float v = src[(long)c * N2n + n0 + tx];
        v = fmaxf(fmaf(v, g_scale[s * MIDn + c], g_shift[s * MIDn + c]), 0.f);
        sm[cl][tx] = v;
    }
    __syncthreads();
    const long base = (long)blockIdx.z * N2n * MIDn;
#pragma unroll
    for (int i = 0; i < 4; i++) {
        const int n = n0 + ty + i * 8;
        __nv_bfloat16 h, l; bf16_split(sm[tx][ty + i * 8], h, l);
        const long a = base + (long)n * MIDn + c0 + tx;
        g_sfHi[a] = h; g_sfLo[a] = l;
    }
}

// =====================================================================
// 3-NN: 512 threads, two halves split the neighbor list, sorted-top3
// merge replays candidates in scan order (bit-identical to full scan).
// =====================================================================
__global__ __launch_bounds__(512)
void knn_kernel(const float* __restrict__ oxyz,
                const float* __restrict__ xyzs)
{
    const int zz = blockIdx.y;
    const int b = zz / L1n, t1 = zz % L1n;
    const int M = c_cnt[t1] * N2n;

    __shared__ float4 nb[1024];
    __shared__ float sd[2][256][3];
    __shared__ int   si[2][256][3];

    for (int j = threadIdx.x; j < M; j += 512) {
        const int sl = c_start[t1] + (j >> 9);
        const int t2 = sl / 3;
        const int n = j & 511;
        const float* p = xyzs + (((long)b * L2n + t2) * N2n + n) * 3;
        const float x = p[0], y = p[1], zc = p[2];
        nb[j] = make_float4(x, y, zc, x * x + y * y + zc * zc);
    }
    __syncthreads();

    const int la = threadIdx.x & 255;
    const int half = threadIdx.x >> 8;
    const int n1 = blockIdx.x * 256 + la;
    const float* a = oxyz + (((long)b * L1n + t1) * N1n + n1) * 3;
    const float ax = a[0], ay = a[1], az = a[2];
    const float an = ax * ax + ay * ay + az * az;

    const int jb = half * (M >> 1), je = jb + (M >> 1);
    float d0 = 1e30f, d1 = 1e30f, d2 = 1e30f;
    int i0 = 0, i1 = 0, i2 = 0;
    for (int j = jb; j < je; j++) {
        const float4 q = nb[j];
        const float d = an + q.w - 2.f * (ax * q.x + ay * q.y + az * q.z);
        if (d < d2) {
            if (d < d1) {
                d2 = d1; i2 = i1;
                if (d < d0) { d1 = d0; i1 = i0; d0 = d; i0 = j; }
                else        { d1 = d;  i1 = j; }
            } else { d2 = d; i2 = j; }
        }
    }
    sd[half][la][0] = d0; sd[half][la][1] = d1; sd[half][la][2] = d2;
    si[half][la][0] = i0; si[half][la][1] = i1; si[half][la][2] = i2;
    __syncthreads();

    if (half == 0) {
        float e0 = 1e30f, e1 = 1e30f, e2 = 1e30f;
        int j0 = 0, j1 = 0, j2 = 0;
#pragma unroll
        for (int h = 0; h < 2; h++)
#pragma unroll
            for (int k = 0; k < 3; k++) {
                const float d = sd[h][la][k];
                const int   j = si[h][la][k];
                if (d < e2) {
                    if (d < e1) {
                        e2 = e1; j2 = j1;
                        if (d < e0) { e1 = e0; j1 = j0; e0 = d; j0 = j; }
                        else        { e1 = d;  j1 = j; }
                    } else { e2 = d; j2 = j; }
                }
            }
        const float s0 = sqrtf(fmaxf(e0, 1e-12f));
        const float s1 = sqrtf(fmaxf(e1, 1e-12f));
        const float s2 = sqrtf(fmaxf(e2, 1e-12f));
        float w0 = 1.f / (s0 + 1e-8f);
        float w1 = 1.f / (s1 + 1e-8f);
        float w2 = 1.f / (s2 + 1e-8f);
        const float inv = 1.f / (w0 + w1 + w2);
        const long base = ((long)zz * N1n + n1) * 3;
        g_idx[base] = j0; g_idx[base + 1] = j1; g_idx[base + 2] = j2;
        g_w[base] = w0 * inv; g_w[base + 1] = w1 * inv; g_w[base + 2] = w2 * inv;
    }
}

// =====================================================================
// launch — two-stream orchestration (capture-safe fork/join via events)
// =====================================================================
extern "C" void kernel_launch(void* const* d_in, const int* in_sizes, int n_in,
                              void* d_out, int out_size)
{
    const float* xyzs  = (const float*)d_in[0];
    const float* oxyz  = (const float*)d_in[1];
    const float* feat  = (const float*)d_in[2];
    const float* ofeat = (const float*)d_in[3];
    const float* Wt    = (const float*)d_in[4];
    const float* gamma = (const float*)d_in[5];
    const float* beta  = (const float*)d_in[6];
    const float* Ws    = (const float*)d_in[7];
    float* out = (float*)d_out;

    static cudaStream_t s1 = nullptr;
    static cudaEvent_t evFork = nullptr, evJoin = nullptr;
    if (!s1) {
        cudaStreamCreateWithFlags(&s1, cudaStreamNonBlocking);
        cudaEventCreateWithFlags(&evFork, cudaEventDisableTiming);
        cudaEventCreateWithFlags(&evJoin, cudaEventDisableTiming);
    }

    const long nf_elems = (long)Bn * L1n * OUTn * N1n;
    float* out_nf = out;
    if ((long)out_size > nf_elems) {
        const long off = (long)out_size - nf_elems;   // original_xyzs first
        cudaMemcpyAsync(out, oxyz, off * sizeof(float), cudaMemcpyDeviceToDevice);
        out_nf = out + off;
    }

    cudaFuncSetAttribute(gemm_mma_kernel,
                         cudaFuncAttributeMaxDynamicSharedMemorySize, GEMM_SMEM);
    cudaFuncSetAttribute(gemm_c2_fused_kernel,
                         cudaFuncAttributeMaxDynamicSharedMemorySize, GEMM_SMEM);

    float *p_tf, *p_P, *p_psum, *p_psq;
    __nv_bfloat16 *pWtHi, *pWtLo, *pWsHi, *pWsLo, *pFtHi, *pFtLo,
                  *pSfHi, *pSfLo, *pOfHi, *pOfLo;
    cudaGetSymbolAddress((void**)&p_tf,  g_tf);
    cudaGetSymbolAddress((void**)&p_P,   g_P);
    cudaGetSymbolAddress((void**)&p_psum, g_psum);
    cudaGetSymbolAddress((void**)&p_psq,  g_psq);
    cudaGetSymbolAddress((void**)&pWtHi, g_WtHi);
    cudaGetSymbolAddress((void**)&pWtLo, g_WtLo);
    cudaGetSymbolAddress((void**)&pWsHi, g_WsHi);
    cudaGetSymbolAddress((void**)&pWsLo, g_WsLo);
    cudaGetSymbolAddress((void**)&pFtHi, g_ftHi);
    cudaGetSymbolAddress((void**)&pFtLo, g_ftLo);
    cudaGetSymbolAddress((void**)&pSfHi, g_sfHi);
    cudaGetSymbolAddress((void**)&pSfLo, g_sfLo);
    cudaGetSymbolAddress((void**)&pOfHi, g_ofHi);
    cudaGetSymbolAddress((void**)&pOfLo, g_ofLo);

    // ---- fork side stream ----
    cudaEventRecord(evFork, 0);
    cudaStreamWaitEvent(s1, evFork, 0);

    // ---- side stream (chain 2): Ws split, ofeat transpose, 3-NN ----
    split_kernel<<<(OUTn * KSP + 255) / 256, 256, 0, s1>>>(Ws, pWsHi, pWsLo,
                                                           (long)OUTn * KSP);
    {
        dim3 grid(N1n / 32, CORn / 32, Bn * L1n);
        ofeatT_kernel<<<grid, 256, 0, s1>>>(ofeat);
    }
    {
        dim3 grid(N1n / 256, Bn * L1n);
        knn_kernel<<<grid, 512, 0, s1>>>(oxyz, xyzs);
    }
    cudaEventRecord(evJoin, s1);

    // ---- main stream (chain 1) ----
    split_kernel<<<(KMID * CINn + 255) / 256, 256>>>(Wt, pWtHi, pWtLo, (long)KMID * CINn);
    {
        dim3 grid(N2n / 32, CINn / 32, Bn * L2n);
        featT_kernel<<<grid, 256>>>(feat);
    }
    // temporal GEMM (+ BN partial sums): A=Wt(768x512), B=g_ft per z -> g_tf
    {
        dim3 grid(N2n / 128, KMID / 128, Bn * L2n);
        gemm_mma_kernel<<<grid, 256, GEMM_SMEM>>>(pWtHi, pWtLo, pFtHi, pFtLo, p_tf,
            N2n, CINn, CINn, CINn,
            0L, (long)N2n * CINn, (long)KMID * N2n,
            p_psum, p_psq);
    }
    // BN finalize + apply/transpose/split
    bn_finalize_kernel<<<(L2n * KMID + 255) / 256, 256>>>(gamma, beta);
    {
        dim3 grid(N2n / 32, MIDn / 32, NSL * Bn);
        bn_transpose_kernel<<<grid, 256>>>();
    }

    // ---- join: P-GEMM needs Ws split; C2 needs ofeat/knn too ----
    cudaStreamWaitEvent(0, evJoin, 0);

    // P-GEMM: A=seedf per z(512x256), B=Ws1(512 rows, k=0..255, ld=384) -> g_P
    {
        dim3 grid(OUTn / 128, N2n / 128, NSL * Bn);
        gemm_mma_kernel<<<grid, 256, GEMM_SMEM>>>(pSfHi, pSfLo, pWsHi, pWsLo, p_P,
            OUTn, MIDn, MIDn, KSP,
            (long)N2n * MIDn, 0L, (long)N2n * OUTn,
            nullptr, nullptr);
    }
    // C2-GEMM + fused gather: out = Ws2@ofeat + interp(P)
    {
        dim3 grid(N1n / 128, OUTn / 128, Bn * L1n);
        gemm_c2_fused_kernel<<<grid, 256, GEMM_SMEM>>>(pWsHi + MIDn, pWsLo + MIDn,
            pOfHi, pOfLo, out_nf,
            N1n, CORn, KSP, CORn,
            0L, (long)N1n * CORn, (long)OUTn * N1n);
    }
}

// round 13
// speedup vs baseline: 1.0594x; 1.0594x over previous
#include <cuda_runtime.h>
#include <cuda_bf16.h>
#include <cstdint>

// ---------------- problem constants ----------------
#define Bn   8
#define L1n  7
#define L2n  3
#define N1n  2048
#define N2n  512
#define CINn 512
#define MIDn 256
#define OUTn 512
#define CORn 128
#define Kt   3
#define KMID (Kt*MIDn)   // 768
#define NSL  (L2n*Kt)    // 9
#define KSP  (MIDn+CORn) // 384

__constant__ int c_start[7] = {0,1,2,4,5,7,8};
__constant__ int c_cnt[7]   = {1,1,2,1,2,1,1};

// ---------------- scratch (device globals) ----------------
__device__ float g_tf[(size_t)Bn*L2n*KMID*N2n];      // temporal GEMM out (b,t2,o,n)
__device__ float g_scale[NSL*MIDn];
__device__ float g_shift[NSL*MIDn];
__device__ int   g_idx[(size_t)Bn*L1n*N1n*3];
__device__ float g_w[(size_t)Bn*L1n*N1n*3];
__device__ __align__(16) float g_P[(size_t)NSL*Bn*N2n*OUTn];  // P = seedf @ Ws1^T (s,b,n2,outc)
// BN partial sums: slot = ((z*4+bx)*2+half)*KMID + row   (24*4*2*768)
__device__ float g_psum[24*4*2*KMID];
__device__ float g_psq[24*4*2*KMID];
// bf16 split operands (16B aligned for cp.async)
__device__ __align__(16) __nv_bfloat16 g_WtHi[KMID*CINn], g_WtLo[KMID*CINn];
__device__ __align__(16) __nv_bfloat16 g_WsHi[OUTn*KSP],  g_WsLo[OUTn*KSP];
__device__ __align__(16) __nv_bfloat16 g_ftHi[(size_t)Bn*L2n*N2n*CINn];
__device__ __align__(16) __nv_bfloat16 g_ftLo[(size_t)Bn*L2n*N2n*CINn];   // (z,n,c)
__device__ __align__(16) __nv_bfloat16 g_sfHi[(size_t)NSL*Bn*N2n*MIDn];
__device__ __align__(16) __nv_bfloat16 g_sfLo[(size_t)NSL*Bn*N2n*MIDn];   // seedf (s,b,n,c)
__device__ __align__(16) __nv_bfloat16 g_ofHi[(size_t)Bn*L1n*N1n*CORn];
__device__ __align__(16) __nv_bfloat16 g_ofLo[(size_t)Bn*L1n*N1n*CORn];   // (z,n,c)

// ===================== PTX helpers (base sm_103-safe) =====================
__device__ __forceinline__ uint32_t smem_u32(const void* p) {
    uint32_t a;
    asm("{ .reg .u64 t; cvta.to.shared.u64 t, %1; cvt.u32.u64 %0, t; }" : "=r"(a) : "l"(p));
    return a;
}
__device__ __forceinline__ void cp16(uint32_t dst, const void* src) {
    asm volatile("cp.async.cg.shared.global [%0], [%1], 16;" :: "r"(dst), "l"(src));
}
__device__ __forceinline__ void ldm4(uint32_t* r, uint32_t addr) {
    asm volatile("ldmatrix.sync.aligned.m8n8.x4.shared.b16 {%0,%1,%2,%3}, [%4];"
                 : "=r"(r[0]), "=r"(r[1]), "=r"(r[2]), "=r"(r[3]) : "r"(addr));
}
__device__ __forceinline__ void mma16816(float* d, const uint32_t* a, const uint32_t* b) {
    asm volatile("mma.sync.aligned.m16n8k16.row.col.f32.bf16.bf16.f32 "
                 "{%0,%1,%2,%3}, {%4,%5,%6,%7}, {%8,%9}, {%0,%1,%2,%3};"
                 : "+f"(d[0]), "+f"(d[1]), "+f"(d[2]), "+f"(d[3])
                 : "r"(a[0]), "r"(a[1]), "r"(a[2]), "r"(a[3]), "r"(b[0]), "r"(b[1]));
}

// =====================================================================
// Fused bf16x2 split GEMM core. Tile 128x128, BK=32, 256 threads.
// acc += Ahi*Bhi + Alo*Bhi + Ahi*Blo per staged K-chunk.
// =====================================================================
#define ROWB 80                    // 64B data + 16B pad
#define TILEB (128*ROWB)           // 10240
#define STAGEB (4*TILEB)           // 40960
#define GEMM_SMEM (2*STAGEB)       // 81920

struct GemmCtx {
    const char *pAh, *pAl, *pBh, *pBl;
    int ldA, ldB;
    int m0, n0;
    uint32_t sbase;
    int tid, lane, wid, wm, wn;
};

__device__ __forceinline__ void gemm_loadTile(const GemmCtx& g, int c, int buf) {
    const int k0 = c << 5;
    const uint32_t sd = g.sbase + buf * STAGEB;
#pragma unroll
    for (int t = 0; t < 8; t++) {
        const int tile = t >> 1;
        const int within = ((t & 1) << 8) + g.tid;
        const int row = within >> 2, colB = (within & 3) << 4;
        const char* bp = (tile == 0) ? g.pAh : (tile == 1) ? g.pAl
                       : (tile == 2) ? g.pBh : g.pBl;
        const int rowg = ((tile < 2) ? g.m0 : g.n0) + row;
        const int ld = (tile < 2) ? g.ldA : g.ldB;
        cp16(sd + tile * TILEB + row * ROWB + colB,
             bp + ((long)rowg * ld + k0) * 2 + colB);
    }
    asm volatile("cp.async.commit_group;" ::: "memory");
}

__device__ __forceinline__ void gemm_computeTile(const GemmCtx& g, int buf,
                                                 float acc[2][8][4]) {
    const uint32_t sAh = g.sbase + buf * STAGEB;
    const uint32_t sAl = sAh + TILEB;
    const uint32_t sBh = sAl + TILEB;
    const uint32_t sBl = sBh + TILEB;
    const int lane = g.lane;
#pragma unroll
    for (int ks = 0; ks < 2; ks++) {
        uint32_t aH[2][4], aL[2][4], bT[4][4];
        const uint32_t aoff0 = (g.wm + (lane & 15)) * ROWB + ks * 32 + (lane >> 4) * 16;
        ldm4(aH[0], sAh + aoff0);
        ldm4(aH[1], sAh + aoff0 + 16 * ROWB);
        ldm4(aL[0], sAl + aoff0);
        ldm4(aL[1], sAl + aoff0 + 16 * ROWB);
#pragma unroll
        for (int ib = 0; ib < 4; ib++) {
            const uint32_t row = g.wn + ib * 16 + (lane & 7) + ((lane & 16) ? 8 : 0);
            ldm4(bT[ib], sBh + row * ROWB + ks * 32 + ((lane & 8) ? 16 : 0));
        }
#pragma unroll
        for (int im = 0; im < 2; im++)
#pragma unroll
            for (int in = 0; in < 8; in++)
                mma16816(acc[im][in], aH[im], bT[in >> 1] + (in & 1) * 2);
#pragma unroll
        for (int im = 0; im < 2; im++)
#pragma unroll
            for (int in = 0; in < 8; in++)
                mma16816(acc[im][in], aL[im], bT[in >> 1] + (in & 1) * 2);
#pragma unroll
        for (int ib = 0; ib < 4; ib++) {
            const uint32_t row = g.wn + ib * 16 + (lane & 7) + ((lane & 16) ? 8 : 0);
            ldm4(bT[ib], sBl + row * ROWB + ks * 32 + ((lane & 8) ? 16 : 0));
        }
#pragma unroll
        for (int im = 0; im < 2; im++)
#pragma unroll
            for (int in = 0; in < 8; in++)
                mma16816(acc[im][in], aH[im], bT[in >> 1] + (in & 1) * 2);
    }
}

__device__ __forceinline__ void gemm_init(GemmCtx& g,
    const __nv_bfloat16* Ahi, const __nv_bfloat16* Alo,
    const __nv_bfloat16* Bhi, const __nv_bfloat16* Blo,
    int ldA, int ldB, long strideA, long strideB, void* smem)
{
    const int z = blockIdx.z;
    g.tid = threadIdx.x; g.lane = g.tid & 31; g.wid = g.tid >> 5;
    g.m0 = blockIdx.y * 128; g.n0 = blockIdx.x * 128;
    g.wm = (g.wid & 3) * 32; g.wn = (g.wid >> 2) * 64;
    g.sbase = smem_u32(smem);
    g.pAh = (const char*)(Ahi + (long)z * strideA);
    g.pAl = (const char*)(Alo + (long)z * strideA);
    g.pBh = (const char*)(Bhi + (long)z * strideB);
    g.pBl = (const char*)(Blo + (long)z * strideB);
    g.ldA = ldA; g.ldB = ldB;
}

// single-sync mainloop: load(c+1) issued AFTER the barrier (all warps done
// reading the buffer it overwrites), overlapping with compute(c).
__device__ __forceinline__ void gemm_mainloop(const GemmCtx& g, int Ktot,
                                              float acc[2][8][4]) {
    const int kch = Ktot >> 5;
    gemm_loadTile(g, 0, 0);
    for (int c = 0; c < kch; c++) {
        asm volatile("cp.async.wait_group 0;" ::: "memory");
        __syncthreads();
        if (c + 1 < kch) gemm_loadTile(g, c + 1, (c + 1) & 1);
        gemm_computeTile(g, c & 1, acc);
    }
}

// ---------------- generic GEMM (temporal + P); optional BN partials ----------
__global__ __launch_bounds__(256, 2)
void gemm_mma_kernel(const __nv_bfloat16* __restrict__ Ahi,
                     const __nv_bfloat16* __restrict__ Alo,
                     const __nv_bfloat16* __restrict__ Bhi,
                     const __nv_bfloat16* __restrict__ Blo,
                     float* __restrict__ C,
                     int N, int Ktot, int ldA, int ldB,
                     long strideA, long strideB, long strideC,
                     float* __restrict__ psum, float* __restrict__ psq)
{
    extern __shared__ __align__(16) char smem[];
    GemmCtx g;
    gemm_init(g, Ahi, Alo, Bhi, Blo, ldA, ldB, strideA, strideB, smem);

    float acc[2][8][4];
#pragma unroll
    for (int i = 0; i < 2; i++)
#pragma unroll
        for (int j = 0; j < 8; j++)
#pragma unroll
            for (int q = 0; q < 4; q++) acc[i][j][q] = 0.f;

    gemm_mainloop(g, Ktot, acc);

    float* cz = C + (long)blockIdx.z * strideC;
#pragma unroll
    for (int im = 0; im < 2; im++) {
        const int row = g.m0 + g.wm + im * 16 + (g.lane >> 2);
#pragma unroll
        for (int in = 0; in < 8; in++) {
            const int col = g.n0 + g.wn + in * 8 + (g.lane & 3) * 2;
            *(float2*)(cz + (long)row * N + col) =
                make_float2(acc[im][in][0], acc[im][in][1]);
            *(float2*)(cz + (long)(row + 8) * N + col) =
                make_float2(acc[im][in][2], acc[im][in][3]);
        }
    }

    // ---- optional BN partial sums (temporal GEMM only) ----
    if (psum) {
        const int half = g.wid >> 2;   // which 64-col half (wn/64)
        const long slot = (((long)blockIdx.z * 4 + blockIdx.x) * 2 + half) * KMID;
#pragma unroll
        for (int im = 0; im < 2; im++) {
#pragma unroll
            for (int rr = 0; rr < 2; rr++) {        // row r (+0) and r+8
                float s = 0.f, q = 0.f;
#pragma unroll
                for (int in = 0; in < 8; in++) {
                    const float v0 = acc[im][in][rr * 2];
                    const float v1 = acc[im][in][rr * 2 + 1];
                    s += v0 + v1;
                    q += v0 * v0 + v1 * v1;
                }
                s += __shfl_xor_sync(0xffffffffu, s, 1);
                q += __shfl_xor_sync(0xffffffffu, q, 1);
                s += __shfl_xor_sync(0xffffffffu, s, 2);
                q += __shfl_xor_sync(0xffffffffu, q, 2);
                if ((g.lane & 3) == 0) {
                    const int grow = g.m0 + g.wm + im * 16 + (g.lane >> 2) + rr * 8;
                    psum[slot + grow] = s;
                    psq[slot + grow]  = q;
                }
            }
        }
    }
}

// BN finalize: 2304 channels (t2, o) -> scale/shift
__global__ void bn_finalize_kernel(const float* __restrict__ gamma,
                                   const float* __restrict__ beta)
{
    const int t = blockIdx.x * 256 + threadIdx.x;
    if (t >= L2n * KMID) return;
    const int t2 = t / KMID, o = t % KMID;
    float S = 0.f, Q = 0.f;
    for (int b = 0; b < Bn; b++)
        for (int bx = 0; bx < 4; bx++)
            for (int h = 0; h < 2; h++) {
                const long slot = (((long)(b * 3 + t2) * 4 + bx) * 2 + h) * KMID + o;
                S += g_psum[slot];
                Q += g_psq[slot];
            }
    const float inv = 1.f / (float)(Bn * N2n);
    const float mean = S * inv;
    const float var = Q * inv - mean * mean;
    const float istd = rsqrtf(var + 1e-5f);
    const int k = o >> 8, c = o & 255;
    const int s = t2 * 3 + k;
    const float scl = gamma[c] * istd;
    g_scale[s * MIDn + c] = scl;
    g_shift[s * MIDn + c] = beta[c] - mean * scl;
}

// ---------------- C2 GEMM with fused interp-gather epilogue ----------------
// C[z][outc][n1] = (Ws2 @ ofeat)[outc][n1] + sum_k w_k * P[idx_k(n1)][outc]
#define SMFP 132   // smem gather-tile pitch in floats (16B multiple)

__global__ __launch_bounds__(256, 2)
void gemm_c2_fused_kernel(const __nv_bfloat16* __restrict__ Ahi,
                          const __nv_bfloat16* __restrict__ Alo,
                          const __nv_bfloat16* __restrict__ Bhi,
                          const __nv_bfloat16* __restrict__ Blo,
                          float* __restrict__ C,
                          int N, int Ktot, int ldA, int ldB,
                          long strideA, long strideB, long strideC)
{
    extern __shared__ __align__(16) char smem[];
    GemmCtx g;
    gemm_init(g, Ahi, Alo, Bhi, Blo, ldA, ldB, strideA, strideB, smem);

    float acc[2][8][4];
#pragma unroll
    for (int i = 0; i < 2; i++)
#pragma unroll
        for (int j = 0; j < 8; j++)
#pragma unroll
            for (int q = 0; q < 4; q++) acc[i][j][q] = 0.f;

    gemm_mainloop(g, Ktot, acc);
    __syncthreads();   // all warps done reading GEMM buffers before smf reuse

    // ---- gather stage: reuse smem as sm[anchor 0..127][outc 0..127] ----
    const int zz = blockIdx.z;
    const int b = zz / L1n, t1 = zz % L1n;
    float (*smf)[SMFP] = (float(*)[SMFP])smem;
    const int lane = g.lane, wid = g.wid;

#pragma unroll
    for (int aa = 0; aa < 16; aa++) {
        const int a = wid * 16 + aa;
        const long base = ((long)zz * N1n + g.n0 + a) * 3;
        float4 s = make_float4(0.f, 0.f, 0.f, 0.f);
#pragma unroll
        for (int k = 0; k < 3; k++) {
            const int j = g_idx[base + k];          // uniform per warp iter -> broadcast
            const float wk = g_w[base + k];
            const int sl = c_start[t1] + (j >> 9);
            const int n = j & 511;
            const float4 v = *(const float4*)(g_P +
                (((long)sl * Bn + b) * N2n + n) * OUTn + g.m0 + lane * 4);
            s.x = fmaf(wk, v.x, s.x);
            s.y = fmaf(wk, v.y, s.y);
            s.z = fmaf(wk, v.z, s.z);
            s.w = fmaf(wk, v.w, s.w);
        }
        *(float4*)(&smf[a][lane * 4]) = s;
    }
    __syncthreads();

    // ---- epilogue: out = acc + gathered interp ----
    float* cz = C + (long)zz * strideC;
#pragma unroll
    for (int im = 0; im < 2; im++) {
        const int rl = g.wm + im * 16 + (lane >> 2);     // outc local
        const int row = g.m0 + rl;
#pragma unroll
        for (int in = 0; in < 8; in++) {
            const int cl = g.wn + in * 8 + (lane & 3) * 2;  // anchor local
            const int col = g.n0 + cl;
            *(float2*)(cz + (long)row * N + col) = make_float2(
                acc[im][in][0] + smf[cl][rl],
                acc[im][in][1] + smf[cl + 1][rl]);
            *(float2*)(cz + (long)(row + 8) * N + col) = make_float2(
                acc[im][in][2] + smf[cl][rl + 8],
                acc[im][in][3] + smf[cl + 1][rl + 8]);
        }
    }
}

// =====================================================================
// bf16 hi/lo split helpers + prep kernels
// =====================================================================
__device__ __forceinline__ void bf16_split(float v, __nv_bfloat16& h, __nv_bfloat16& l) {
    h = __float2bfloat16(v);
    l = __float2bfloat16(v - __bfloat162float(h));
}

__global__ void split_kernel(const float* __restrict__ src,
                             __nv_bfloat16* __restrict__ hi,
                             __nv_bfloat16* __restrict__ lo, long n)
{
    const long i = (long)blockIdx.x * 256 + threadIdx.x;
    if (i < n) { __nv_bfloat16 h, l; bf16_split(src[i], h, l); hi[i] = h; lo[i] = l; }
}

// features (z,c=512,n=512) -> g_ft (z,n,c) hi/lo
__global__ void featT_kernel(const float* __restrict__ feat)
{
    __shared__ float sm[32][33];
    const int z = blockIdx.z, n0 = blockIdx.x * 32, c0 = blockIdx.y * 32;
    const int tx = threadIdx.x & 31, ty = threadIdx.x >> 5;
    const float* src = feat + (long)z * CINn * N2n;
#pragma unroll
    for (int i = 0; i < 4; i++)
        sm[ty + i * 8][tx] = src[(long)(c0 + ty + i * 8) * N2n + n0 + tx];
    __syncthreads();
#pragma unroll
    for (int i = 0; i < 4; i++) {
        const int n = n0 + ty + i * 8;
        __nv_bfloat16 h, l; bf16_split(sm[tx][ty + i * 8], h, l);
        const long a = ((long)z * N2n + n) * CINn + c0 + tx;
        g_ftHi[a] = h; g_ftLo[a] = l;
    }
}

// original_features (z,c=128,n=2048) -> g_of (z,n,c) hi/lo
__global__ void ofeatT_kernel(const float* __restrict__ ofeat)
{
    __shared__ float sm[32][33];
    const int z = blockIdx.z, n0 = blockIdx.x * 32, c0 = blockIdx.y * 32;
    const int tx = threadIdx.x & 31, ty = threadIdx.x >> 5;
    const float* src = ofeat + (long)z * CORn * N1n;
#pragma unroll
    for (int i = 0; i < 4; i++)
        sm[ty + i * 8][tx] = src[(long)(c0 + ty + i * 8) * N1n + n0 + tx];
    __syncthreads();
#pragma unroll
    for (int i = 0; i < 4; i++) {
        const int n = n0 + ty + i * 8;
        __nv_bfloat16 h, l; bf16_split(sm[tx][ty + i * 8], h, l);
        const long a = ((long)z * N1n + n) * CORn + c0 + tx;
        g_ofHi[a] = h; g_ofLo[a] = l;
    }
}

// BN apply + ReLU + transpose + split: g_tf (b,t2,o,n) -> g_sf (s,b,n,c) hi/lo
__global__ void bn_transpose_kernel()
{
    __shared__ float sm[32][33];
    const int s = blockIdx.z >> 3, b = blockIdx.z & 7;
    const int t2 = s / 3, k = s % 3;
    const int n0 = blockIdx.x * 32, c0 = blockIdx.y * 32;
    const int tx = threadIdx.x & 31, ty = threadIdx.x >> 5;

    const float* src = g_tf + ((long)(b * L2n + t2) * KMID + k * MIDn) * N2n;
#pragma unroll
    for (int i = 0; i < 4; i++) {
        const int cl = ty + i * 8;
        const int c = c0 + cl;
        float v = src[(long)c * N2n + n0 + tx];
        v = fmaxf(fmaf(v, g_scale[s * MIDn + c], g_shift[s * MIDn + c]), 0.f);
        sm[cl][tx] = v;
    }
    __syncthreads();
    const long base = (long)blockIdx.z * N2n * MIDn;
#pragma unroll
    for (int i = 0; i < 4; i++) {
        const int n = n0 + ty + i * 8;
        __nv_bfloat16 h, l; bf16_split(sm[tx][ty + i * 8], h, l);
        const long a = base + (long)n * MIDn + c0 + tx;
        g_sfHi[a] = h; g_sfLo[a] = l;
    }
}

// =====================================================================
// 3-NN: 512 threads, two halves split the neighbor list, sorted-top3
// merge replays candidates in scan order (bit-identical to full scan).
// =====================================================================
__global__ __launch_bounds__(512)
void knn_kernel(const float* __restrict__ oxyz,
                const float* __restrict__ xyzs)
{
    const int zz = blockIdx.y;
    const int b = zz / L1n, t1 = zz % L1n;
    const int M = c_cnt[t1] * N2n;

    __shared__ float4 nb[1024];
    __shared__ float sd[2][256][3];
    __shared__ int   si[2][256][3];

    for (int j = threadIdx.x; j < M; j += 512) {
        const int sl = c_start[t1] + (j >> 9);
        const int t2 = sl / 3;
        const int n = j & 511;
        const float* p = xyzs + (((long)b * L2n + t2) * N2n + n) * 3;
        const float x = p[0], y = p[1], zc = p[2];
        nb[j] = make_float4(x, y, zc, x * x + y * y + zc * zc);
    }
    __syncthreads();

    const int la = threadIdx.x & 255;
    const int half = threadIdx.x >> 8;
    const int n1 = blockIdx.x * 256 + la;
    const float* a = oxyz + (((long)b * L1n + t1) * N1n + n1) * 3;
    const float ax = a[0], ay = a[1], az = a[2];
    const float an = ax * ax + ay * ay + az * az;

    const int jb = half * (M >> 1), je = jb + (M >> 1);
    float d0 = 1e30f, d1 = 1e30f, d2 = 1e30f;
    int i0 = 0, i1 = 0, i2 = 0;
    for (int j = jb; j < je; j++) {
        const float4 q = nb[j];
        const float d = an + q.w - 2.f * (ax * q.x + ay * q.y + az * q.z);
        if (d < d2) {
            if (d < d1) {
                d2 = d1; i2 = i1;
                if (d < d0) { d1 = d0; i1 = i0; d0 = d; i0 = j; }
                else        { d1 = d;  i1 = j; }
            } else { d2 = d; i2 = j; }
        }
    }
    sd[half][la][0] = d0; sd[half][la][1] = d1; sd[half][la][2] = d2;
    si[half][la][0] = i0; si[half][la][1] = i1; si[half][la][2] = i2;
    __syncthreads();

    if (half == 0) {
        float e0 = 1e30f, e1 = 1e30f, e2 = 1e30f;
        int j0 = 0, j1 = 0, j2 = 0;
#pragma unroll
        for (int h = 0; h < 2; h++)
#pragma unroll
            for (int k = 0; k < 3; k++) {
                const float d = sd[h][la][k];
                const int   j = si[h][la][k];
                if (d < e2) {
                    if (d < e1) {
                        e2 = e1; j2 = j1;
                        if (d < e0) { e1 = e0; j1 = j0; e0 = d; j0 = j; }
                        else        { e1 = d;  j1 = j; }
                    } else { e2 = d; j2 = j; }
                }
            }
        const float s0 = sqrtf(fmaxf(e0, 1e-12f));
        const float s1 = sqrtf(fmaxf(e1, 1e-12f));
        const float s2 = sqrtf(fmaxf(e2, 1e-12f));
        float w0 = 1.f / (s0 + 1e-8f);
        float w1 = 1.f / (s1 + 1e-8f);
        float w2 = 1.f / (s2 + 1e-8f);
        const float inv = 1.f / (w0 + w1 + w2);
        const long base = ((long)zz * N1n + n1) * 3;
        g_idx[base] = j0; g_idx[base + 1] = j1; g_idx[base + 2] = j2;
        g_w[base] = w0 * inv; g_w[base + 1] = w1 * inv; g_w[base + 2] = w2 * inv;
    }
}

// =====================================================================
// launch — two-stream orchestration (capture-safe fork/join via events)
// =====================================================================
extern "C" void kernel_launch(void* const* d_in, const int* in_sizes, int n_in,
                              void* d_out, int out_size)
{
    const float* xyzs  = (const float*)d_in[0];
    const float* oxyz  = (const float*)d_in[1];
    const float* feat  = (const float*)d_in[2];
    const float* ofeat = (const float*)d_in[3];
    const float* Wt    = (const float*)d_in[4];
    const float* gamma = (const float*)d_in[5];
    const float* beta  = (const float*)d_in[6];
    const float* Ws    = (const float*)d_in[7];
    float* out = (float*)d_out;

    static cudaStream_t s1 = nullptr;
    static cudaEvent_t evFork = nullptr, evJoin = nullptr;
    if (!s1) {
        cudaStreamCreateWithFlags(&s1, cudaStreamNonBlocking);
        cudaEventCreateWithFlags(&evFork, cudaEventDisableTiming);
        cudaEventCreateWithFlags(&evJoin, cudaEventDisableTiming);
    }

    cudaFuncSetAttribute(gemm_mma_kernel,
                         cudaFuncAttributeMaxDynamicSharedMemorySize, GEMM_SMEM);
    cudaFuncSetAttribute(gemm_c2_fused_kernel,
                         cudaFuncAttributeMaxDynamicSharedMemorySize, GEMM_SMEM);

    float *p_tf, *p_P, *p_psum, *p_psq;
    __nv_bfloat16 *pWtHi, *pWtLo, *pWsHi, *pWsLo, *pFtHi, *pFtLo,
                  *pSfHi, *pSfLo, *pOfHi, *pOfLo;
    cudaGetSymbolAddress((void**)&p_tf,  g_tf);
    cudaGetSymbolAddress((void**)&p_P,   g_P);
    cudaGetSymbolAddress((void**)&p_psum, g_psum);
    cudaGetSymbolAddress((void**)&p_psq,  g_psq);
    cudaGetSymbolAddress((void**)&pWtHi, g_WtHi);
    cudaGetSymbolAddress((void**)&pWtLo, g_WtLo);
    cudaGetSymbolAddress((void**)&pWsHi, g_WsHi);
    cudaGetSymbolAddress((void**)&pWsLo, g_WsLo);
    cudaGetSymbolAddress((void**)&pFtHi, g_ftHi);
    cudaGetSymbolAddress((void**)&pFtLo, g_ftLo);
    cudaGetSymbolAddress((void**)&pSfHi, g_sfHi);
    cudaGetSymbolAddress((void**)&pSfLo, g_sfLo);
    cudaGetSymbolAddress((void**)&pOfHi, g_ofHi);
    cudaGetSymbolAddress((void**)&pOfLo, g_ofLo);

    const long nf_elems = (long)Bn * L1n * OUTn * N1n;
    float* out_nf = out;

    // ---- fork side stream ----
    cudaEventRecord(evFork, 0);
    cudaStreamWaitEvent(s1, evFork, 0);

    // ---- side stream (chain 2): xyz copy, Ws split, ofeat transpose, 3-NN ----
    if ((long)out_size > nf_elems) {
        const long off = (long)out_size - nf_elems;   // original_xyzs first
        cudaMemcpyAsync(out, oxyz, off * sizeof(float),
                        cudaMemcpyDeviceToDevice, s1);
        out_nf = out + off;
    }
    split_kernel<<<(OUTn * KSP + 255) / 256, 256, 0, s1>>>(Ws, pWsHi, pWsLo,
                                                           (long)OUTn * KSP);
    {
        dim3 grid(N1n / 32, CORn / 32, Bn * L1n);
        ofeatT_kernel<<<grid, 256, 0, s1>>>(ofeat);
    }
    {
        dim3 grid(N1n / 256, Bn * L1n);
        knn_kernel<<<grid, 512, 0, s1>>>(oxyz, xyzs);
    }
    cudaEventRecord(evJoin, s1);

    // ---- main stream (chain 1) ----
    split_kernel<<<(KMID * CINn + 255) / 256, 256>>>(Wt, pWtHi, pWtLo, (long)KMID * CINn);
    {
        dim3 grid(N2n / 32, CINn / 32, Bn * L2n);
        featT_kernel<<<grid, 256>>>(feat);
    }
    // temporal GEMM (+ BN partial sums): A=Wt(768x512), B=g_ft per z -> g_tf
    {
        dim3 grid(N2n / 128, KMID / 128, Bn * L2n);
        gemm_mma_kernel<<<grid, 256, GEMM_SMEM>>>(pWtHi, pWtLo, pFtHi, pFtLo, p_tf,
            N2n, CINn, CINn, CINn,
            0L, (long)N2n * CINn, (long)KMID * N2n,
            p_psum, p_psq);
    }
    // BN finalize + apply/transpose/split
    bn_finalize_kernel<<<(L2n * KMID + 255) / 256, 256>>>(gamma, beta);
    {
        dim3 grid(N2n / 32, MIDn / 32, NSL * Bn);
        bn_transpose_kernel<<<grid, 256>>>();
    }

    // ---- join: P-GEMM needs Ws split; C2 needs ofeat/knn too ----
    cudaStreamWaitEvent(0, evJoin, 0);

    // P-GEMM: A=seedf per z(512x256), B=Ws1(512 rows, k=0..255, ld=384) -> g_P
    {
        dim3 grid(OUTn / 128, N2n / 128, NSL * Bn);
        gemm_mma_kernel<<<grid, 256, GEMM_SMEM>>>(pSfHi, pSfLo, pWsHi, pWsLo, p_P,
            OUTn, MIDn, MIDn, KSP,
            (long)N2n * MIDn, 0L, (long)N2n * OUTn,
            nullptr, nullptr);
    }
    // C2-GEMM + fused gather: out = Ws2@ofeat + interp(P)
    {
        dim3 grid(N1n / 128, OUTn / 128, Bn * L1n);
        gemm_c2_fused_kernel<<<grid, 256, GEMM_SMEM>>>(pWsHi + MIDn, pWsLo + MIDn,
            pOfHi, pOfLo, out_nf,
            N1n, CORn, KSP, CORn,
            0L, (long)N1n * CORn, (long)OUTn * N1n);
    }
}

// round 14
// speedup vs baseline: 1.5071x; 1.4227x over previous
#include <cuda_runtime.h>
#include <cuda_fp16.h>
#include <cstdint>

// ---------------- problem constants ----------------
#define Bn   8
#define L1n  7
#define L2n  3
#define N1n  2048
#define N2n  512
#define CINn 512
#define MIDn 256
#define OUTn 512
#define CORn 128
#define Kt   3
#define KMID (Kt*MIDn)   // 768
#define NSL  (L2n*Kt)    // 9
#define KSP  (MIDn+CORn) // 384

__constant__ int c_start[7] = {0,1,2,4,5,7,8};
__constant__ int c_cnt[7]   = {1,1,2,1,2,1,1};

// ---------------- scratch (device globals) ----------------
__device__ float g_tf[(size_t)Bn*L2n*KMID*N2n];      // temporal GEMM out (b,t2,o,n)
__device__ float g_scale[NSL*MIDn];
__device__ float g_shift[NSL*MIDn];
__device__ int   g_idx[(size_t)Bn*L1n*N1n*3];
__device__ float g_w[(size_t)Bn*L1n*N1n*3];
__device__ __align__(16) float g_P[(size_t)NSL*Bn*N2n*OUTn];  // P = seedf @ Ws1^T (s,b,n2,outc)
// BN partial sums: slot = ((z*4+bx)*2+half)*KMID + row
__device__ float g_psum[24*4*2*KMID];
__device__ float g_psq[24*4*2*KMID];
// fp16 operands (16B aligned for cp.async)
__device__ __align__(16) __half g_Wt16[KMID*CINn];
__device__ __align__(16) __half g_Ws16[OUTn*KSP];
__device__ __align__(16) __half g_ft16[(size_t)Bn*L2n*N2n*CINn];   // (z,n,c)
__device__ __align__(16) __half g_sf16[(size_t)NSL*Bn*N2n*MIDn];   // seedf (s,b,n,c)
__device__ __align__(16) __half g_of16[(size_t)Bn*L1n*N1n*CORn];   // (z,n,c)

// ===================== PTX helpers (base sm_103-safe) =====================
__device__ __forceinline__ uint32_t smem_u32(const void* p) {
    uint32_t a;
    asm("{ .reg .u64 t; cvta.to.shared.u64 t, %1; cvt.u32.u64 %0, t; }" : "=r"(a) : "l"(p));
    return a;
}
__device__ __forceinline__ void cp16(uint32_t dst, const void* src) {
    asm volatile("cp.async.cg.shared.global [%0], [%1], 16;" :: "r"(dst), "l"(src));
}
__device__ __forceinline__ void ldm4(uint32_t* r, uint32_t addr) {
    asm volatile("ldmatrix.sync.aligned.m8n8.x4.shared.b16 {%0,%1,%2,%3}, [%4];"
                 : "=r"(r[0]), "=r"(r[1]), "=r"(r[2]), "=r"(r[3]) : "r"(addr));
}
__device__ __forceinline__ void mma16816h(float* d, const uint32_t* a, const uint32_t* b) {
    asm volatile("mma.sync.aligned.m16n8k16.row.col.f32.f16.f16.f32 "
                 "{%0,%1,%2,%3}, {%4,%5,%6,%7}, {%8,%9}, {%0,%1,%2,%3};"
                 : "+f"(d[0]), "+f"(d[1]), "+f"(d[2]), "+f"(d[3])
                 : "r"(a[0]), "r"(a[1]), "r"(a[2]), "r"(a[3]), "r"(b[0]), "r"(b[1]));
}

// =====================================================================
// Single-pass fp16 GEMM core. Tile 128x128, BK=32, 256 threads,
// fp32 accumulate. C[z][m][n] = sum_k A[z][m][k]*B[z][n][k].
// =====================================================================
#define ROWB 80                    // 64B data + 16B pad
#define TILEB (128*ROWB)           // 10240
#define STAGEB (2*TILEB)           // 20480 (A + B)
#define GEMM_SMEM (2*STAGEB)       // 40960

struct GemmCtx {
    const char *pA, *pB;
    int ldA, ldB;
    int m0, n0;
    uint32_t sbase;
    int tid, lane, wid, wm, wn;
};

__device__ __forceinline__ void gemm_loadTile(const GemmCtx& g, int c, int buf) {
    const int k0 = c << 5;
    const uint32_t sd = g.sbase + buf * STAGEB;
#pragma unroll
    for (int t = 0; t < 4; t++) {
        const int tile = t >> 1;                     // 0 = A, 1 = B
        const int within = ((t & 1) << 8) + g.tid;   // 0..511
        const int row = within >> 2, colB = (within & 3) << 4;
        const char* bp = (tile == 0) ? g.pA : g.pB;
        const int rowg = ((tile == 0) ? g.m0 : g.n0) + row;
        const int ld = (tile == 0) ? g.ldA : g.ldB;
        cp16(sd + tile * TILEB + row * ROWB + colB,
             bp + ((long)rowg * ld + k0) * 2 + colB);
    }
    asm volatile("cp.async.commit_group;" ::: "memory");
}

__device__ __forceinline__ void gemm_computeTile(const GemmCtx& g, int buf,
                                                 float acc[2][8][4]) {
    const uint32_t sA = g.sbase + buf * STAGEB;
    const uint32_t sB = sA + TILEB;
    const int lane = g.lane;
#pragma unroll
    for (int ks = 0; ks < 2; ks++) {
        uint32_t a[2][4], bT[4][4];
        const uint32_t aoff0 = (g.wm + (lane & 15)) * ROWB + ks * 32 + (lane >> 4) * 16;
        ldm4(a[0], sA + aoff0);
        ldm4(a[1], sA + aoff0 + 16 * ROWB);
#pragma unroll
        for (int ib = 0; ib < 4; ib++) {
            const uint32_t row = g.wn + ib * 16 + (lane & 7) + ((lane & 16) ? 8 : 0);
            ldm4(bT[ib], sB + row * ROWB + ks * 32 + ((lane & 8) ? 16 : 0));
        }
#pragma unroll
        for (int im = 0; im < 2; im++)
#pragma unroll
            for (int in = 0; in < 8; in++)
                mma16816h(acc[im][in], a[im], bT[in >> 1] + (in & 1) * 2);
    }
}

__device__ __forceinline__ void gemm_init(GemmCtx& g,
    const __half* A, const __half* B,
    int ldA, int ldB, long strideA, long strideB, void* smem)
{
    const int z = blockIdx.z;
    g.tid = threadIdx.x; g.lane = g.tid & 31; g.wid = g.tid >> 5;
    g.m0 = blockIdx.y * 128; g.n0 = blockIdx.x * 128;
    g.wm = (g.wid & 3) * 32; g.wn = (g.wid >> 2) * 64;
    g.sbase = smem_u32(smem);
    g.pA = (const char*)(A + (long)z * strideA);
    g.pB = (const char*)(B + (long)z * strideB);
    g.ldA = ldA; g.ldB = ldB;
}

__device__ __forceinline__ void gemm_mainloop(const GemmCtx& g, int Ktot,
                                              float acc[2][8][4]) {
    const int kch = Ktot >> 5;
    gemm_loadTile(g, 0, 0);
    for (int c = 0; c < kch; c++) {
        asm volatile("cp.async.wait_group 0;" ::: "memory");
        __syncthreads();
        if (c + 1 < kch) gemm_loadTile(g, c + 1, (c + 1) & 1);
        gemm_computeTile(g, c & 1, acc);
    }
}

// ---------------- generic GEMM (temporal + P); optional BN partials ----------
__global__ __launch_bounds__(256, 2)
void gemm_mma_kernel(const __half* __restrict__ A,
                     const __half* __restrict__ B,
                     float* __restrict__ C,
                     int N, int Ktot, int ldA, int ldB,
                     long strideA, long strideB, long strideC,
                     float* __restrict__ psum, float* __restrict__ psq)
{
    extern __shared__ __align__(16) char smem[];
    GemmCtx g;
    gemm_init(g, A, B, ldA, ldB, strideA, strideB, smem);

    float acc[2][8][4];
#pragma unroll
    for (int i = 0; i < 2; i++)
#pragma unroll
        for (int j = 0; j < 8; j++)
#pragma unroll
            for (int q = 0; q < 4; q++) acc[i][j][q] = 0.f;

    gemm_mainloop(g, Ktot, acc);

    float* cz = C + (long)blockIdx.z * strideC;
#pragma unroll
    for (int im = 0; im < 2; im++) {
        const int row = g.m0 + g.wm + im * 16 + (g.lane >> 2);
#pragma unroll
        for (int in = 0; in < 8; in++) {
            const int col = g.n0 + g.wn + in * 8 + (g.lane & 3) * 2;
            *(float2*)(cz + (long)row * N + col) =
                make_float2(acc[im][in][0], acc[im][in][1]);
            *(float2*)(cz + (long)(row + 8) * N + col) =
                make_float2(acc[im][in][2], acc[im][in][3]);
        }
    }

    // ---- optional BN partial sums (temporal GEMM only) ----
    if (psum) {
        const int half = g.wid >> 2;
        const long slot = (((long)blockIdx.z * 4 + blockIdx.x) * 2 + half) * KMID;
#pragma unroll
        for (int im = 0; im < 2; im++) {
#pragma unroll
            for (int rr = 0; rr < 2; rr++) {
                float s = 0.f, q = 0.f;
#pragma unroll
                for (int in = 0; in < 8; in++) {
                    const float v0 = acc[im][in][rr * 2];
                    const float v1 = acc[im][in][rr * 2 + 1];
                    s += v0 + v1;
                    q += v0 * v0 + v1 * v1;
                }
                s += __shfl_xor_sync(0xffffffffu, s, 1);
                q += __shfl_xor_sync(0xffffffffu, q, 1);
                s += __shfl_xor_sync(0xffffffffu, s, 2);
                q += __shfl_xor_sync(0xffffffffu, q, 2);
                if ((g.lane & 3) == 0) {
                    const int grow = g.m0 + g.wm + im * 16 + (g.lane >> 2) + rr * 8;
                    psum[slot + grow] = s;
                    psq[slot + grow]  = q;
                }
            }
        }
    }
}

// BN finalize: 2304 channels (t2, o) -> scale/shift
__global__ void bn_finalize_kernel(const float* __restrict__ gamma,
                                   const float* __restrict__ beta)
{
    const int t = blockIdx.x * 256 + threadIdx.x;
    if (t >= L2n * KMID) return;
    const int t2 = t / KMID, o = t % KMID;
    float S = 0.f, Q = 0.f;
    for (int b = 0; b < Bn; b++)
        for (int bx = 0; bx < 4; bx++)
            for (int h = 0; h < 2; h++) {
                const long slot = (((long)(b * 3 + t2) * 4 + bx) * 2 + h) * KMID + o;
                S += g_psum[slot];
                Q += g_psq[slot];
            }
    const float inv = 1.f / (float)(Bn * N2n);
    const float mean = S * inv;
    const float var = Q * inv - mean * mean;
    const float istd = rsqrtf(var + 1e-5f);
    const int k = o >> 8, c = o & 255;
    const int s = t2 * 3 + k;
    const float scl = gamma[c] * istd;
    g_scale[s * MIDn + c] = scl;
    g_shift[s * MIDn + c] = beta[c] - mean * scl;
}

// ---------------- C2 GEMM with fused interp-gather epilogue ----------------
// C[z][outc][n1] = (Ws2 @ ofeat)[outc][n1] + sum_k w_k * P[idx_k(n1)][outc]
#define SMFP 132   // smem gather-tile pitch in floats (16B multiple); 128*132*4 = 67584 <= fits

__global__ __launch_bounds__(256, 2)
void gemm_c2_fused_kernel(const __half* __restrict__ A,
                          const __half* __restrict__ B,
                          float* __restrict__ C,
                          int N, int Ktot, int ldA, int ldB,
                          long strideA, long strideB, long strideC)
{
    extern __shared__ __align__(16) char smem[];
    GemmCtx g;
    gemm_init(g, A, B, ldA, ldB, strideA, strideB, smem);

    float acc[2][8][4];
#pragma unroll
    for (int i = 0; i < 2; i++)
#pragma unroll
        for (int j = 0; j < 8; j++)
#pragma unroll
            for (int q = 0; q < 4; q++) acc[i][j][q] = 0.f;

    gemm_mainloop(g, Ktot, acc);
    __syncthreads();   // all warps done reading GEMM buffers before smf reuse

    // ---- gather stage: smem as sm[anchor 0..127][outc 0..127] (67.6KB) ----
    const int zz = blockIdx.z;
    const int b = zz / L1n, t1 = zz % L1n;
    float (*smf)[SMFP] = (float(*)[SMFP])smem;
    const int lane = g.lane, wid = g.wid;

#pragma unroll
    for (int aa = 0; aa < 16; aa++) {
        const int a = wid * 16 + aa;
        const long base = ((long)zz * N1n + g.n0 + a) * 3;
        float4 s = make_float4(0.f, 0.f, 0.f, 0.f);
#pragma unroll
        for (int k = 0; k < 3; k++) {
            const int j = g_idx[base + k];
            const float wk = g_w[base + k];
            const int sl = c_start[t1] + (j >> 9);
            const int n = j & 511;
            const float4 v = *(const float4*)(g_P +
                (((long)sl * Bn + b) * N2n + n) * OUTn + g.m0 + lane * 4);
            s.x = fmaf(wk, v.x, s.x);
            s.y = fmaf(wk, v.y, s.y);
            s.z = fmaf(wk, v.z, s.z);
            s.w = fmaf(wk, v.w, s.w);
        }
        *(float4*)(&smf[a][lane * 4]) = s;
    }
    __syncthreads();

    // ---- epilogue: out = acc + gathered interp ----
    float* cz = C + (long)zz * strideC;
#pragma unroll
    for (int im = 0; im < 2; im++) {
        const int rl = g.wm + im * 16 + (lane >> 2);
        const int row = g.m0 + rl;
#pragma unroll
        for (int in = 0; in < 8; in++) {
            const int cl = g.wn + in * 8 + (lane & 3) * 2;
            const int col = g.n0 + cl;
            *(float2*)(cz + (long)row * N + col) = make_float2(
                acc[im][in][0] + smf[cl][rl],
                acc[im][in][1] + smf[cl + 1][rl]);
            *(float2*)(cz + (long)(row + 8) * N + col) = make_float2(
                acc[im][in][2] + smf[cl][rl + 8],
                acc[im][in][3] + smf[cl + 1][rl + 8]);
        }
    }
}

// =====================================================================
// prep kernels (fp32 -> fp16)
// =====================================================================
__global__ void cvt_kernel(const float* __restrict__ src,
                           __half* __restrict__ dst, long n)
{
    const long i = (long)blockIdx.x * 256 + threadIdx.x;
    if (i < n) dst[i] = __float2half(src[i]);
}

// features (z,c=512,n=512) -> g_ft16 (z,n,c)
__global__ void featT_kernel(const float* __restrict__ feat)
{
    __shared__ float sm[32][33];
    const int z = blockIdx.z, n0 = blockIdx.x * 32, c0 = blockIdx.y * 32;
    const int tx = threadIdx.x & 31, ty = threadIdx.x >> 5;
    const float* src = feat + (long)z * CINn * N2n;
#pragma unroll
    for (int i = 0; i < 4; i++)
        sm[ty + i * 8][tx] = src[(long)(c0 + ty + i * 8) * N2n + n0 + tx];
    __syncthreads();
#pragma unroll
    for (int i = 0; i < 4; i++) {
        const int n = n0 + ty + i * 8;
        g_ft16[((long)z * N2n + n) * CINn + c0 + tx] = __float2half(sm[tx][ty + i * 8]);
    }
}

// original_features (z,c=128,n=2048) -> g_of16 (z,n,c)
__global__ void ofeatT_kernel(const float* __restrict__ ofeat)
{
    __shared__ float sm[32][33];
    const int z = blockIdx.z, n0 = blockIdx.x * 32, c0 = blockIdx.y * 32;
    const int tx = threadIdx.x & 31, ty = threadIdx.x >> 5;
    const float* src = ofeat + (long)z * CORn * N1n;
#pragma unroll
    for (int i = 0; i < 4; i++)
        sm[ty + i * 8][tx] = src[(long)(c0 + ty + i * 8) * N1n + n0 + tx];
    __syncthreads();
#pragma unroll
    for (int i = 0; i < 4; i++) {
        const int n = n0 + ty + i * 8;
        g_of16[((long)z * N1n + n) * CORn + c0 + tx] = __float2half(sm[tx][ty + i * 8]);
    }
}

// BN apply + ReLU + transpose: g_tf (b,t2,o,n) -> g_sf16 (s,b,n,c)
__global__ void bn_transpose_kernel()
{
    __shared__ float sm[32][33];
    const int s = blockIdx.z >> 3, b = blockIdx.z & 7;
    const int t2 = s / 3, k = s % 3;
    const int n0 = blockIdx.x * 32, c0 = blockIdx.y * 32;
    const int tx = threadIdx.x & 31, ty = threadIdx.x >> 5;

    const float* src = g_tf + ((long)(b * L2n + t2) * KMID + k * MIDn) * N2n;
#pragma unroll
    for (int i = 0; i < 4; i++) {
        const int cl = ty + i * 8;
        const int c = c0 + cl;
        float v = src[(long)c * N2n + n0 + tx];
        v = fmaxf(fmaf(v, g_scale[s * MIDn + c], g_shift[s * MIDn + c]), 0.f);
        sm[cl][tx] = v;
    }
    __syncthreads();
    const long base = (long)blockIdx.z * N2n * MIDn;
#pragma unroll
    for (int i = 0; i < 4; i++) {
        const int n = n0 + ty + i * 8;
        g_sf16[base + (long)n * MIDn + c0 + tx] = __float2half(sm[tx][ty + i * 8]);
    }
}

// =====================================================================
// 3-NN: 512 threads, two halves split the neighbor list, sorted-top3
// merge replays candidates in scan order (bit-identical to full scan).
// =====================================================================
__global__ __launch_bounds__(512)
void knn_kernel(const float* __restrict__ oxyz,
                const float* __restrict__ xyzs)
{
    const int zz = blockIdx.y;
    const int b = zz / L1n, t1 = zz % L1n;
    const int M = c_cnt[t1] * N2n;

    __shared__ float4 nb[1024];
    __shared__ float sd[2][256][3];
    __shared__ int   si[2][256][3];

    for (int j = threadIdx.x; j < M; j += 512) {
        const int sl = c_start[t1] + (j >> 9);
        const int t2 = sl / 3;
        const int n = j & 511;
        const float* p = xyzs + (((long)b * L2n + t2) * N2n + n) * 3;
        const float x = p[0], y = p[1], zc = p[2];
        nb[j] = make_float4(x, y, zc, x * x + y * y + zc * zc);
    }
    __syncthreads();

    const int la = threadIdx.x & 255;
    const int half = threadIdx.x >> 8;
    const int n1 = blockIdx.x * 256 + la;
    const float* a = oxyz + (((long)b * L1n + t1) * N1n + n1) * 3;
    const float ax = a[0], ay = a[1], az = a[2];
    const float an = ax * ax + ay * ay + az * az;

    const int jb = half * (M >> 1), je = jb + (M >> 1);
    float d0 = 1e30f, d1 = 1e30f, d2 = 1e30f;
    int i0 = 0, i1 = 0, i2 = 0;
    for (int j = jb; j < je; j++) {
        const float4 q = nb[j];
        const float d = an + q.w - 2.f * (ax * q.x + ay * q.y + az * q.z);
        if (d < d2) {
            if (d < d1) {
                d2 = d1; i2 = i1;
                if (d < d0) { d1 = d0; i1 = i0; d0 = d; i0 = j; }
                else        { d1 = d;  i1 = j; }
            } else { d2 = d; i2 = j; }
        }
    }
    sd[half][la][0] = d0; sd[half][la][1] = d1; sd[half][la][2] = d2;
    si[half][la][0] = i0; si[half][la][1] = i1; si[half][la][2] = i2;
    __syncthreads();

    if (half == 0) {
        float e0 = 1e30f, e1 = 1e30f, e2 = 1e30f;
        int j0 = 0, j1 = 0, j2 = 0;
#pragma unroll
        for (int h = 0; h < 2; h++)
#pragma unroll
            for (int k = 0; k < 3; k++) {
                const float d = sd[h][la][k];
                const int   j = si[h][la][k];
                if (d < e2) {
                    if (d < e1) {
                        e2 = e1; j2 = j1;
                        if (d < e0) { e1 = e0; j1 = j0; e0 = d; j0 = j; }
                        else        { e1 = d;  j1 = j; }
                    } else { e2 = d; j2 = j; }
                }
            }
        const float s0 = sqrtf(fmaxf(e0, 1e-12f));
        const float s1 = sqrtf(fmaxf(e1, 1e-12f));
        const float s2 = sqrtf(fmaxf(e2, 1e-12f));
        float w0 = 1.f / (s0 + 1e-8f);
        float w1 = 1.f / (s1 + 1e-8f);
        float w2 = 1.f / (s2 + 1e-8f);
        const float inv = 1.f / (w0 + w1 + w2);
        const long base = ((long)zz * N1n + n1) * 3;
        g_idx[base] = j0; g_idx[base + 1] = j1; g_idx[base + 2] = j2;
        g_w[base] = w0 * inv; g_w[base + 1] = w1 * inv; g_w[base + 2] = w2 * inv;
    }
}

// =====================================================================
// launch — two-stream orchestration (capture-safe fork/join via events)
// =====================================================================
extern "C" void kernel_launch(void* const* d_in, const int* in_sizes, int n_in,
                              void* d_out, int out_size)
{
    const float* xyzs  = (const float*)d_in[0];
    const float* oxyz  = (const float*)d_in[1];
    const float* feat  = (const float*)d_in[2];
    const float* ofeat = (const float*)d_in[3];
    const float* Wt    = (const float*)d_in[4];
    const float* gamma = (const float*)d_in[5];
    const float* beta  = (const float*)d_in[6];
    const float* Ws    = (const float*)d_in[7];
    float* out = (float*)d_out;

    static cudaStream_t s1 = nullptr;
    static cudaEvent_t evFork = nullptr, evJoin = nullptr;
    if (!s1) {
        cudaStreamCreateWithFlags(&s1, cudaStreamNonBlocking);
        cudaEventCreateWithFlags(&evFork, cudaEventDisableTiming);
        cudaEventCreateWithFlags(&evJoin, cudaEventDisableTiming);
    }

    cudaFuncSetAttribute(gemm_mma_kernel,
                         cudaFuncAttributeMaxDynamicSharedMemorySize, GEMM_SMEM);
    cudaFuncSetAttribute(gemm_c2_fused_kernel,
                         cudaFuncAttributeMaxDynamicSharedMemorySize, 128 * SMFP * 4);

    float *p_tf, *p_P, *p_psum, *p_psq;
    __half *pWt16, *pWs16, *pFt16, *pSf16, *pOf16;
    cudaGetSymbolAddress((void**)&p_tf,  g_tf);
    cudaGetSymbolAddress((void**)&p_P,   g_P);
    cudaGetSymbolAddress((void**)&p_psum, g_psum);
    cudaGetSymbolAddress((void**)&p_psq,  g_psq);
    cudaGetSymbolAddress((void**)&pWt16, g_Wt16);
    cudaGetSymbolAddress((void**)&pWs16, g_Ws16);
    cudaGetSymbolAddress((void**)&pFt16, g_ft16);
    cudaGetSymbolAddress((void**)&pSf16, g_sf16);
    cudaGetSymbolAddress((void**)&pOf16, g_of16);

    const long nf_elems = (long)Bn * L1n * OUTn * N1n;
    float* out_nf = out;

    // ---- fork side stream ----
    cudaEventRecord(evFork, 0);
    cudaStreamWaitEvent(s1, evFork, 0);

    // ---- side stream (chain 2): xyz copy, Ws cvt, ofeat transpose, 3-NN ----
    if ((long)out_size > nf_elems) {
        const long off = (long)out_size - nf_elems;   // original_xyzs first
        cudaMemcpyAsync(out, oxyz, off * sizeof(float),
                        cudaMemcpyDeviceToDevice, s1);
        out_nf = out + off;
    }
    cvt_kernel<<<(OUTn * KSP + 255) / 256, 256, 0, s1>>>(Ws, pWs16, (long)OUTn * KSP);
    {
        dim3 grid(N1n / 32, CORn / 32, Bn * L1n);
        ofeatT_kernel<<<grid, 256, 0, s1>>>(ofeat);
    }
    {
        dim3 grid(N1n / 256, Bn * L1n);
        knn_kernel<<<grid, 512, 0, s1>>>(oxyz, xyzs);
    }
    cudaEventRecord(evJoin, s1);

    // ---- main stream (chain 1) ----
    cvt_kernel<<<(KMID * CINn + 255) / 256, 256>>>(Wt, pWt16, (long)KMID * CINn);
    {
        dim3 grid(N2n / 32, CINn / 32, Bn * L2n);
        featT_kernel<<<grid, 256>>>(feat);
    }
    // temporal GEMM (+ BN partial sums): A=Wt(768x512), B=g_ft per z -> g_tf
    {
        dim3 grid(N2n / 128, KMID / 128, Bn * L2n);
        gemm_mma_kernel<<<grid, 256, GEMM_SMEM>>>(pWt16, pFt16, p_tf,
            N2n, CINn, CINn, CINn,
            0L, (long)N2n * CINn, (long)KMID * N2n,
            p_psum, p_psq);
    }
    // BN finalize + apply/transpose
    bn_finalize_kernel<<<(L2n * KMID + 255) / 256, 256>>>(gamma, beta);
    {
        dim3 grid(N2n / 32, MIDn / 32, NSL * Bn);
        bn_transpose_kernel<<<grid, 256>>>();
    }

    // ---- join: P-GEMM needs Ws; C2 needs ofeat/knn too ----
    cudaStreamWaitEvent(0, evJoin, 0);

    // P-GEMM: A=seedf per z(512x256), B=Ws1(512 rows, k=0..255, ld=384) -> g_P
    {
        dim3 grid(OUTn / 128, N2n / 128, NSL * Bn);
        gemm_mma_kernel<<<grid, 256, GEMM_SMEM>>>(pSf16, pWs16, p_P,
            OUTn, MIDn, MIDn, KSP,
            (long)N2n * MIDn, 0L, (long)N2n * OUTn,
            nullptr, nullptr);
    }
    // C2-GEMM + fused gather: out = Ws2@ofeat + interp(P)
    {
        dim3 grid(N1n / 128, OUTn / 128, Bn * L1n);
        gemm_c2_fused_kernel<<<grid, 256, 128 * SMFP * 4>>>(pWs16 + MIDn,
            pOf16, out_nf,
            N1n, CORn, KSP, CORn,
            0L, (long)N1n * CORn, (long)OUTn * N1n);
    }
}

// round 16
// speedup vs baseline: 1.5685x; 1.0407x over previous
#include <cuda_runtime.h>
#include <cuda_fp16.h>
#include <cstdint>

// ---------------- problem constants ----------------
#define Bn   8
#define L1n  7
#define L2n  3
#define N1n  2048
#define N2n  512
#define CINn 512
#define MIDn 256
#define OUTn 512
#define CORn 128
#define Kt   3
#define KMID (Kt*MIDn)   // 768
#define NSL  (L2n*Kt)    // 9
#define KSP  (MIDn+CORn) // 384

__constant__ int c_start[7] = {0,1,2,4,5,7,8};
__constant__ int c_cnt[7]   = {1,1,2,1,2,1,1};

// ---------------- scratch (device globals) ----------------
__device__ float g_tf[(size_t)Bn*L2n*KMID*N2n];      // temporal GEMM out (b,t2,o,n)
__device__ float g_scale[NSL*MIDn];
__device__ float g_shift[NSL*MIDn];
__device__ int   g_idx[(size_t)Bn*L1n*N1n*3];
__device__ float g_w[(size_t)Bn*L1n*N1n*3];
__device__ __align__(16) __half g_P16[(size_t)NSL*Bn*N2n*OUTn];  // P = seedf @ Ws1^T (fp16)
// BN partial sums: slot = ((z*4+bx)*2+half)*KMID + row
__device__ float g_psum[24*4*2*KMID];
__device__ float g_psq[24*4*2*KMID];
// fp16 operands (16B aligned for cp.async)
__device__ __align__(16) __half g_Wt16[KMID*CINn];
__device__ __align__(16) __half g_Ws16[OUTn*KSP];
__device__ __align__(16) __half g_ft16[(size_t)Bn*L2n*N2n*CINn];   // (z,n,c)
__device__ __align__(16) __half g_sf16[(size_t)NSL*Bn*N2n*MIDn];   // seedf (s,b,n,c)
__device__ __align__(16) __half g_of16[(size_t)Bn*L1n*N1n*CORn];   // (z,n,c)

// ===================== PTX helpers (base sm_103-safe) =====================
__device__ __forceinline__ uint32_t smem_u32(const void* p) {
    uint32_t a;
    asm("{ .reg .u64 t; cvta.to.shared.u64 t, %1; cvt.u32.u64 %0, t; }" : "=r"(a) : "l"(p));
    return a;
}
__device__ __forceinline__ void cp16(uint32_t dst, const void* src) {
    asm volatile("cp.async.cg.shared.global [%0], [%1], 16;" :: "r"(dst), "l"(src));
}
__device__ __forceinline__ void ldm4(uint32_t* r, uint32_t addr) {
    asm volatile("ldmatrix.sync.aligned.m8n8.x4.shared.b16 {%0,%1,%2,%3}, [%4];"
                 : "=r"(r[0]), "=r"(r[1]), "=r"(r[2]), "=r"(r[3]) : "r"(addr));
}
__device__ __forceinline__ void mma16816h(float* d, const uint32_t* a, const uint32_t* b) {
    asm volatile("mma.sync.aligned.m16n8k16.row.col.f32.f16.f16.f32 "
                 "{%0,%1,%2,%3}, {%4,%5,%6,%7}, {%8,%9}, {%0,%1,%2,%3};"
                 : "+f"(d[0]), "+f"(d[1]), "+f"(d[2]), "+f"(d[3])
                 : "r"(a[0]), "r"(a[1]), "r"(a[2]), "r"(a[3]), "r"(b[0]), "r"(b[1]));
}

// =====================================================================
// Single-pass fp16 GEMM core. Tile 128x128, BK=32, 256 threads,
// fp32 accumulate. C[z][m][n] = sum_k A[z][m][k]*B[z][n][k].
// =====================================================================
#define ROWB 80                    // 64B data + 16B pad
#define TILEB (128*ROWB)           // 10240
#define STAGEB (2*TILEB)           // 20480 (A + B)
#define GEMM_SMEM (2*STAGEB)       // 40960

struct GemmCtx {
    const char *pA, *pB;
    int ldA, ldB;
    int m0, n0;
    uint32_t sbase;
    int tid, lane, wid, wm, wn;
};

__device__ __forceinline__ void gemm_loadTile(const GemmCtx& g, int c, int buf) {
    const int k0 = c << 5;
    const uint32_t sd = g.sbase + buf * STAGEB;
#pragma unroll
    for (int t = 0; t < 4; t++) {
        const int tile = t >> 1;                     // 0 = A, 1 = B
        const int within = ((t & 1) << 8) + g.tid;   // 0..511
        const int row = within >> 2, colB = (within & 3) << 4;
        const char* bp = (tile == 0) ? g.pA : g.pB;
        const int rowg = ((tile == 0) ? g.m0 : g.n0) + row;
        const int ld = (tile == 0) ? g.ldA : g.ldB;
        cp16(sd + tile * TILEB + row * ROWB + colB,
             bp + ((long)rowg * ld + k0) * 2 + colB);
    }
    asm volatile("cp.async.commit_group;" ::: "memory");
}

__device__ __forceinline__ void gemm_computeTile(const GemmCtx& g, int buf,
                                                 float acc[2][8][4]) {
    const uint32_t sA = g.sbase + buf * STAGEB;
    const uint32_t sB = sA + TILEB;
    const int lane = g.lane;
#pragma unroll
    for (int ks = 0; ks < 2; ks++) {
        uint32_t a[2][4], bT[4][4];
        const uint32_t aoff0 = (g.wm + (lane & 15)) * ROWB + ks * 32 + (lane >> 4) * 16;
        ldm4(a[0], sA + aoff0);
        ldm4(a[1], sA + aoff0 + 16 * ROWB);
#pragma unroll
        for (int ib = 0; ib < 4; ib++) {
            const uint32_t row = g.wn + ib * 16 + (lane & 7) + ((lane & 16) ? 8 : 0);
            ldm4(bT[ib], sB + row * ROWB + ks * 32 + ((lane & 8) ? 16 : 0));
        }
#pragma unroll
        for (int im = 0; im < 2; im++)
#pragma unroll
            for (int in = 0; in < 8; in++)
                mma16816h(acc[im][in], a[im], bT[in >> 1] + (in & 1) * 2);
    }
}

__device__ __forceinline__ void gemm_init(GemmCtx& g,
    const __half* A, const __half* B,
    int ldA, int ldB, long strideA, long strideB, void* smem)
{
    const int z = blockIdx.z;
    g.tid = threadIdx.x; g.lane = g.tid & 31; g.wid = g.tid >> 5;
    g.m0 = blockIdx.y * 128; g.n0 = blockIdx.x * 128;
    g.wm = (g.wid & 3) * 32; g.wn = (g.wid >> 2) * 64;
    g.sbase = smem_u32(smem);
    g.pA = (const char*)(A + (long)z * strideA);
    g.pB = (const char*)(B + (long)z * strideB);
    g.ldA = ldA; g.ldB = ldB;
}

__device__ __forceinline__ void gemm_mainloop(const GemmCtx& g, int Ktot,
                                              float acc[2][8][4]) {
    const int kch = Ktot >> 5;
    gemm_loadTile(g, 0, 0);
    for (int c = 0; c < kch; c++) {
        asm volatile("cp.async.wait_group 0;" ::: "memory");
        __syncthreads();
        if (c + 1 < kch) gemm_loadTile(g, c + 1, (c + 1) & 1);
        gemm_computeTile(g, c & 1, acc);
    }
}

// ---------------- generic GEMM; fp32 OR fp16 output; optional BN partials ----
__global__ __launch_bounds__(256, 2)
void gemm_mma_kernel(const __half* __restrict__ A,
                     const __half* __restrict__ B,
                     float* __restrict__ C,
                     __half* __restrict__ Ch,
                     int N, int Ktot, int ldA, int ldB,
                     long strideA, long strideB, long strideC,
                     float* __restrict__ psum, float* __restrict__ psq)
{
    extern __shared__ __align__(16) char smem[];
    GemmCtx g;
    gemm_init(g, A, B, ldA, ldB, strideA, strideB, smem);

    float acc[2][8][4];
#pragma unroll
    for (int i = 0; i < 2; i++)
#pragma unroll
        for (int j = 0; j < 8; j++)
#pragma unroll
            for (int q = 0; q < 4; q++) acc[i][j][q] = 0.f;

    gemm_mainloop(g, Ktot, acc);

    if (Ch) {
        __half* cz = Ch + (long)blockIdx.z * strideC;
#pragma unroll
        for (int im = 0; im < 2; im++) {
            const int row = g.m0 + g.wm + im * 16 + (g.lane >> 2);
#pragma unroll
            for (int in = 0; in < 8; in++) {
                const int col = g.n0 + g.wn + in * 8 + (g.lane & 3) * 2;
                *(__half2*)(cz + (long)row * N + col) =
                    __floats2half2_rn(acc[im][in][0], acc[im][in][1]);
                *(__half2*)(cz + (long)(row + 8) * N + col) =
                    __floats2half2_rn(acc[im][in][2], acc[im][in][3]);
            }
        }
    } else {
        float* cz = C + (long)blockIdx.z * strideC;
#pragma unroll
        for (int im = 0; im < 2; im++) {
            const int row = g.m0 + g.wm + im * 16 + (g.lane >> 2);
#pragma unroll
            for (int in = 0; in < 8; in++) {
                const int col = g.n0 + g.wn + in * 8 + (g.lane & 3) * 2;
                *(float2*)(cz + (long)row * N + col) =
                    make_float2(acc[im][in][0], acc[im][in][1]);
                *(float2*)(cz + (long)(row + 8) * N + col) =
                    make_float2(acc[im][in][2], acc[im][in][3]);
            }
        }
    }

    // ---- optional BN partial sums (temporal GEMM only) ----
    if (psum) {
        const int half = g.wid >> 2;
        const long slot = (((long)blockIdx.z * 4 + blockIdx.x) * 2 + half) * KMID;
#pragma unroll
        for (int im = 0; im < 2; im++) {
#pragma unroll
            for (int rr = 0; rr < 2; rr++) {
                float s = 0.f, q = 0.f;
#pragma unroll
                for (int in = 0; in < 8; in++) {
                    const float v0 = acc[im][in][rr * 2];
                    const float v1 = acc[im][in][rr * 2 + 1];
                    s += v0 + v1;
                    q += v0 * v0 + v1 * v1;
                }
                s += __shfl_xor_sync(0xffffffffu, s, 1);
                q += __shfl_xor_sync(0xffffffffu, q, 1);
                s += __shfl_xor_sync(0xffffffffu, s, 2);
                q += __shfl_xor_sync(0xffffffffu, q, 2);
                if ((g.lane & 3) == 0) {
                    const int grow = g.m0 + g.wm + im * 16 + (g.lane >> 2) + rr * 8;
                    psum[slot + grow] = s;
                    psq[slot + grow]  = q;
                }
            }
        }
    }
}

// BN finalize: 2304 channels (t2, o) -> scale/shift
__global__ void bn_finalize_kernel(const float* __restrict__ gamma,
                                   const float* __restrict__ beta)
{
    const int t = blockIdx.x * 256 + threadIdx.x;
    if (t >= L2n * KMID) return;
    const int t2 = t / KMID, o = t % KMID;
    float S = 0.f, Q = 0.f;
    for (int b = 0; b < Bn; b++)
        for (int bx = 0; bx < 4; bx++)
            for (int h = 0; h < 2; h++) {
                const long slot = (((long)(b * 3 + t2) * 4 + bx) * 2 + h) * KMID + o;
                S += g_psum[slot];
                Q += g_psq[slot];
            }
    const float inv = 1.f / (float)(Bn * N2n);
    const float mean = S * inv;
    const float var = Q * inv - mean * mean;
    const float istd = rsqrtf(var + 1e-5f);
    const int k = o >> 8, c = o & 255;
    const int s = t2 * 3 + k;
    const float scl = gamma[c] * istd;
    g_scale[s * MIDn + c] = scl;
    g_shift[s * MIDn + c] = beta[c] - mean * scl;
}

// ---------------- C2 GEMM with fused interp-gather epilogue ----------------
// C[z][outc][n1] = (Ws2 @ ofeat)[outc][n1] + sum_k w_k * P16[idx_k(n1)][outc]
#define SMFP 132   // smem gather-tile pitch in floats (16B multiple)

__global__ __launch_bounds__(256, 2)
void gemm_c2_fused_kernel(const __half* __restrict__ A,
                          const __half* __restrict__ B,
                          float* __restrict__ C,
                          int N, int Ktot, int ldA, int ldB,
                          long strideA, long strideB, long strideC)
{
    extern __shared__ __align__(16) char smem[];
    GemmCtx g;
    gemm_init(g, A, B, ldA, ldB, strideA, strideB, smem);

    float acc[2][8][4];
#pragma unroll
    for (int i = 0; i < 2; i++)
#pragma unroll
        for (int j = 0; j < 8; j++)
#pragma unroll
            for (int q = 0; q < 4; q++) acc[i][j][q] = 0.f;

    gemm_mainloop(g, Ktot, acc);
    __syncthreads();   // all warps done reading GEMM buffers before smf reuse

    // ---- gather stage: smem as sm[anchor 0..127][outc 0..127] (67.6KB) ----
    const int zz = blockIdx.z;
    const int b = zz / L1n, t1 = zz % L1n;
    float (*smf)[SMFP] = (float(*)[SMFP])smem;
    const int lane = g.lane, wid = g.wid;

#pragma unroll
    for (int aa = 0; aa < 16; aa++) {
        const int a = wid * 16 + aa;
        const long base = ((long)zz * N1n + g.n0 + a) * 3;
        float4 s = make_float4(0.f, 0.f, 0.f, 0.f);
#pragma unroll
        for (int k = 0; k < 3; k++) {
            const int j = g_idx[base + k];
            const float wk = g_w[base + k];
            const int sl = c_start[t1] + (j >> 9);
            const int n = j & 511;
            // 4 halves (outc lane*4..lane*4+3) = 8B load
            const uint2 u = *(const uint2*)(g_P16 +
                (((long)sl * Bn + b) * N2n + n) * OUTn + g.m0 + lane * 4);
            const float2 f01 = __half22float2(*(const __half2*)&u.x);
            const float2 f23 = __half22float2(*(const __half2*)&u.y);
            s.x = fmaf(wk, f01.x, s.x);
            s.y = fmaf(wk, f01.y, s.y);
            s.z = fmaf(wk, f23.x, s.z);
            s.w = fmaf(wk, f23.y, s.w);
        }
        *(float4*)(&smf[a][lane * 4]) = s;
    }
    __syncthreads();

    // ---- epilogue: out = acc + gathered interp ----
    float* cz = C + (long)zz * strideC;
#pragma unroll
    for (int im = 0; im < 2; im++) {
        const int rl = g.wm + im * 16 + (lane >> 2);
        const int row = g.m0 + rl;
#pragma unroll
        for (int in = 0; in < 8; in++) {
            const int cl = g.wn + in * 8 + (lane & 3) * 2;
            const int col = g.n0 + cl;
            *(float2*)(cz + (long)row * N + col) = make_float2(
                acc[im][in][0] + smf[cl][rl],
                acc[im][in][1] + smf[cl + 1][rl]);
            *(float2*)(cz + (long)(row + 8) * N + col) = make_float2(
                acc[im][in][2] + smf[cl][rl + 8],
                acc[im][in][3] + smf[cl + 1][rl + 8]);
        }
    }
}

// =====================================================================
// prep kernels (fp32 -> fp16)
// =====================================================================
__global__ void cvt_kernel(const float* __restrict__ src,
                           __half* __restrict__ dst, long n)
{
    const long i = (long)blockIdx.x * 256 + threadIdx.x;
    if (i < n) dst[i] = __float2half(src[i]);
}

// features (z,c=512,n=512) -> g_ft16 (z,n,c)
__global__ void featT_kernel(const float* __restrict__ feat)
{
    __shared__ float sm[32][33];
    const int z = blockIdx.z, n0 = blockIdx.x * 32, c0 = blockIdx.y * 32;
    const int tx = threadIdx.x & 31, ty = threadIdx.x >> 5;
    const float* src = feat + (long)z * CINn * N2n;
#pragma unroll
    for (int i = 0; i < 4; i++)
        sm[ty + i * 8][tx] = src[(long)(c0 + ty + i * 8) * N2n + n0 + tx];
    __syncthreads();
#pragma unroll
    for (int i = 0; i < 4; i++) {
        const int n = n0 + ty + i * 8;
        g_ft16[((long)z * N2n + n) * CINn + c0 + tx] = __float2half(sm[tx][ty + i * 8]);
    }
}

// original_features (z,c=128,n=2048) -> g_of16 (z,n,c)
__global__ void ofeatT_kernel(const float* __restrict__ ofeat)
{
    __shared__ float sm[32][33];
    const int z = blockIdx.z, n0 = blockIdx.x * 32, c0 = blockIdx.y * 32;
    const int tx = threadIdx.x & 31, ty = threadIdx.x >> 5;
    const float* src = ofeat + (long)z * CORn * N1n;
#pragma unroll
    for (int i = 0; i < 4; i++)
        sm[ty + i * 8][tx] = src[(long)(c0 + ty + i * 8) * N1n + n0 + tx];
    __syncthreads();
#pragma unroll
    for (int i = 0; i < 4; i++) {
        const int n = n0 + ty + i * 8;
        g_of16[((long)z * N1n + n) * CORn + c0 + tx] = __float2half(sm[tx][ty + i * 8]);
    }
}

// BN apply + ReLU + transpose: g_tf (b,t2,o,n) -> g_sf16 (s,b,n,c)
__global__ void bn_transpose_kernel()
{
    __shared__ float sm[32][33];
    const int s = blockIdx.z >> 3, b = blockIdx.z & 7;
    const int t2 = s / 3, k = s % 3;
    const int n0 = blockIdx.x * 32, c0 = blockIdx.y * 32;
    const int tx = threadIdx.x & 31, ty = threadIdx.x >> 5;

    const float* src = g_tf + ((long)(b * L2n + t2) * KMID + k * MIDn) * N2n;
#pragma unroll
    for (int i = 0; i < 4; i++) {
        const int cl = ty + i * 8;
        const int c = c0 + cl;
        float v = src[(long)c * N2n + n0 + tx];
        v = fmaxf(fmaf(v, g_scale[s * MIDn + c], g_shift[s * MIDn + c]), 0.f);
        sm[cl][tx] = v;
    }
    __syncthreads();
    const long base = (long)blockIdx.z * N2n * MIDn;
#pragma unroll
    for (int i = 0; i < 4; i++) {
        const int n = n0 + ty + i * 8;
        g_sf16[base + (long)n * MIDn + c0 + tx] = __float2half(sm[tx][ty + i * 8]);
    }
}

// =====================================================================
// 3-NN: 512 threads, two halves split the neighbor list, sorted-top3
// merge replays candidates in scan order (bit-identical to full scan).
// =====================================================================
__global__ __launch_bounds__(512)
void knn_kernel(const float* __restrict__ oxyz,
                const float* __restrict__ xyzs)
{
    const int zz = blockIdx.y;
    const int b = zz / L1n, t1 = zz % L1n;
    const int M = c_cnt[t1] * N2n;

    __shared__ float4 nb[1024];
    __shared__ float sd[2][256][3];
    __shared__ int   si[2][256][3];

    for (int j = threadIdx.x; j < M; j += 512) {
        const int sl = c_start[t1] + (j >> 9);
        const int t2 = sl / 3;
        const int n = j & 511;
        const float* p = xyzs + (((long)b * L2n + t2) * N2n + n) * 3;
        const float x = p[0], y = p[1], zc = p[2];
        nb[j] = make_float4(x, y, zc, x * x + y * y + zc * zc);
    }
    __syncthreads();

    const int la = threadIdx.x & 255;
    const int half = threadIdx.x >> 8;
    const int n1 = blockIdx.x * 256 + la;
    const float* a = oxyz + (((long)b * L1n + t1) * N1n + n1) * 3;
    const float ax = a[0], ay = a[1], az = a[2];
    const float an = ax * ax + ay * ay + az * az;

    const int jb = half * (M >> 1), je = jb + (M >> 1);
    float d0 = 1e30f, d1 = 1e30f, d2 = 1e30f;
    int i0 = 0, i1 = 0, i2 = 0;
    for (int j = jb; j < je; j++) {
        const float4 q = nb[j];
        const float d = an + q.w - 2.f * (ax * q.x + ay * q.y + az * q.z);
        if (d < d2) {
            if (d < d1) {
                d2 = d1; i2 = i1;
                if (d < d0) { d1 = d0; i1 = i0; d0 = d; i0 = j; }
                else        { d1 = d;  i1 = j; }
            } else { d2 = d; i2 = j; }
        }
    }
    sd[half][la][0] = d0; sd[half][la][1] = d1; sd[half][la][2] = d2;
    si[half][la][0] = i0; si[half][la][1] = i1; si[half][la][2] = i2;
    __syncthreads();

    if (half == 0) {
        float e0 = 1e30f, e1 = 1e30f, e2 = 1e30f;
        int j0 = 0, j1 = 0, j2 = 0;
#pragma unroll
        for (int h = 0; h < 2; h++)
#pragma unroll
            for (int k = 0; k < 3; k++) {
                const float d = sd[h][la][k];
                const int   j = si[h][la][k];
                if (d < e2) {
                    if (d < e1) {
                        e2 = e1; j2 = j1;
                        if (d < e0) { e1 = e0; j1 = j0; e0 = d; j0 = j; }
                        else        { e1 = d;  j1 = j; }
                    } else { e2 = d; j2 = j; }
                }
            }
        const float s0 = sqrtf(fmaxf(e0, 1e-12f));
        const float s1 = sqrtf(fmaxf(e1, 1e-12f));
        const float s2 = sqrtf(fmaxf(e2, 1e-12f));
        float w0 = 1.f / (s0 + 1e-8f);
        float w1 = 1.f / (s1 + 1e-8f);
        float w2 = 1.f / (s2 + 1e-8f);
        const float inv = 1.f / (w0 + w1 + w2);
        const long base = ((long)zz * N1n + n1) * 3;
        g_idx[base] = j0; g_idx[base + 1] = j1; g_idx[base + 2] = j2;
        g_w[base] = w0 * inv; g_w[base + 1] = w1 * inv; g_w[base + 2] = w2 * inv;
    }
}

// =====================================================================
// launch — two-stream orchestration (capture-safe fork/join via events)
// =====================================================================
extern "C" void kernel_launch(void* const* d_in, const int* in_sizes, int n_in,
                              void* d_out, int out_size)
{
    const float* xyzs  = (const float*)d_in[0];
    const float* oxyz  = (const float*)d_in[1];
    const float* feat  = (const float*)d_in[2];
    const float* ofeat = (const float*)d_in[3];
    const float* Wt    = (const float*)d_in[4];
    const float* gamma = (const float*)d_in[5];
    const float* beta  = (const float*)d_in[6];
    const float* Ws    = (const float*)d_in[7];
    float* out = (float*)d_out;

    static cudaStream_t s1 = nullptr;
    static cudaEvent_t evFork = nullptr, evJoin = nullptr;
    if (!s1) {
        cudaStreamCreateWithFlags(&s1, cudaStreamNonBlocking);
        cudaEventCreateWithFlags(&evFork, cudaEventDisableTiming);
        cudaEventCreateWithFlags(&evJoin, cudaEventDisableTiming);
    }

    cudaFuncSetAttribute(gemm_mma_kernel,
                         cudaFuncAttributeMaxDynamicSharedMemorySize, GEMM_SMEM);
    cudaFuncSetAttribute(gemm_c2_fused_kernel,
                         cudaFuncAttributeMaxDynamicSharedMemorySize, 128 * SMFP * 4);

    float *p_tf, *p_psum, *p_psq;
    __half *p_P16, *pWt16, *pWs16, *pFt16, *pSf16, *pOf16;
    cudaGetSymbolAddress((void**)&p_tf,  g_tf);
    cudaGetSymbolAddress((void**)&p_P16, g_P16);
    cudaGetSymbolAddress((void**)&p_psum, g_psum);
    cudaGetSymbolAddress((void**)&p_psq,  g_psq);
    cudaGetSymbolAddress((void**)&pWt16, g_Wt16);
    cudaGetSymbolAddress((void**)&pWs16, g_Ws16);
    cudaGetSymbolAddress((void**)&pFt16, g_ft16);
    cudaGetSymbolAddress((void**)&pSf16, g_sf16);
    cudaGetSymbolAddress((void**)&pOf16, g_of16);

    const long nf_elems = (long)Bn * L1n * OUTn * N1n;
    float* out_nf = out;

    // ---- fork side stream ----
    cudaEventRecord(evFork, 0);
    cudaStreamWaitEvent(s1, evFork, 0);

    // ---- side stream (chain 2): xyz copy, Ws cvt, ofeat transpose, 3-NN ----
    if ((long)out_size > nf_elems) {
        const long off = (long)out_size - nf_elems;   // original_xyzs first
        cudaMemcpyAsync(out, oxyz, off * sizeof(float),
                        cudaMemcpyDeviceToDevice, s1);
        out_nf = out + off;
    }
    cvt_kernel<<<(OUTn * KSP + 255) / 256, 256, 0, s1>>>(Ws, pWs16, (long)OUTn * KSP);
    {
        dim3 grid(N1n / 32, CORn / 32, Bn * L1n);
        ofeatT_kernel<<<grid, 256, 0, s1>>>(ofeat);
    }
    {
        dim3 grid(N1n / 256, Bn * L1n);
        knn_kernel<<<grid, 512, 0, s1>>>(oxyz, xyzs);
    }
    cudaEventRecord(evJoin, s1);

    // ---- main stream (chain 1) ----
    cvt_kernel<<<(KMID * CINn + 255) / 256, 256>>>(Wt, pWt16, (long)KMID * CINn);
    {
        dim3 grid(N2n / 32, CINn / 32, Bn * L2n);
        featT_kernel<<<grid, 256>>>(feat);
    }
    // temporal GEMM (+ BN partial sums): A=Wt(768x512), B=g_ft per z -> g_tf (fp32)
    {
        dim3 grid(N2n / 128, KMID / 128, Bn * L2n);
        gemm_mma_kernel<<<grid, 256, GEMM_SMEM>>>(pWt16, pFt16, p_tf, nullptr,
            N2n, CINn, CINn, CINn,
            0L, (long)N2n * CINn, (long)KMID * N2n,
            p_psum, p_psq);
    }
    // BN finalize + apply/transpose
    bn_finalize_kernel<<<(L2n * KMID + 255) / 256, 256>>>(gamma, beta);
    {
        dim3 grid(N2n / 32, MIDn / 32, NSL * Bn);
        bn_transpose_kernel<<<grid, 256>>>();
    }

    // ---- join: P-GEMM needs Ws; C2 needs ofeat/knn too ----
    cudaStreamWaitEvent(0, evJoin, 0);

    // P-GEMM: A=seedf per z(512x256), B=Ws1(512 rows, k=0..255, ld=384) -> g_P16 (fp16)
    {
        dim3 grid(OUTn / 128, N2n / 128, NSL * Bn);
        gemm_mma_kernel<<<grid, 256, GEMM_SMEM>>>(pSf16, pWs16, nullptr, p_P16,
            OUTn, MIDn, MIDn, KSP,
            (long)N2n * MIDn, 0L, (long)N2n * OUTn,
            nullptr, nullptr);
    }
    // C2-GEMM + fused gather: out = Ws2@ofeat + interp(P16)
    {
        dim3 grid(N1n / 128, OUTn / 128, Bn * L1n);
        gemm_c2_fused_kernel<<<grid, 256, 128 * SMFP * 4>>>(pWs16 + MIDn,
            pOf16, out_nf,
            N1n, CORn, KSP, CORn,
            0L, (long)N1n * CORn, (long)OUTn * N1n);
    }
}